// round 10
// baseline (speedup 1.0000x reference)
#include <cuda_runtime.h>
#include <cuda_fp16.h>
#include <math.h>
#include <stdint.h>

#define BB 4
#define SS 4096
#define HH 128
#define ROWS_TOTAL (BB * SS)

// Scratch (allocation-free path). Q pre-scaled by 1/sqrt(H). All fp16.
// V stored transposed: g_Vt[b][h][s].
__device__ __half g_Q[ROWS_TOTAL * HH];
__device__ __half g_K[ROWS_TOTAL * HH];
__device__ __half g_Vt[BB * HH * SS];

__device__ __forceinline__ float to_tf32(float x) {
    uint32_t u;
    asm("cvt.rna.tf32.f32 %0, %1;" : "=r"(u) : "f"(x));
    return __uint_as_float(u);
}

__device__ __forceinline__ uint32_t smem_u32_of(const void* p) {
    uint32_t a;
    asm("{ .reg .u64 t; cvta.to.shared.u64 t, %1; cvt.u32.u64 %0, t; }" : "=r"(a) : "l"(p));
    return a;
}

__device__ __forceinline__ void cp_async16(uint32_t dst, const void* src) {
    asm volatile("cp.async.cg.shared.global [%0], [%1], 16;" :: "r"(dst), "l"(src));
}
#define CP_COMMIT() asm volatile("cp.async.commit_group;" ::: "memory")
#define CP_WAIT0()  asm volatile("cp.async.wait_group 0;" ::: "memory")

// tf32 m16n8k8 (for QKV projection; validated R3-R9)
__device__ __forceinline__ void mma_tf32(float* d, const uint32_t* a,
                                         uint32_t b0, uint32_t b1) {
    asm volatile(
        "mma.sync.aligned.m16n8k8.row.col.f32.tf32.tf32.f32 "
        "{%0,%1,%2,%3}, {%4,%5,%6,%7}, {%8,%9}, {%0,%1,%2,%3};"
        : "+f"(d[0]), "+f"(d[1]), "+f"(d[2]), "+f"(d[3])
        : "r"(a[0]), "r"(a[1]), "r"(a[2]), "r"(a[3]), "r"(b0), "r"(b1));
}

// fp16 m16n8k16 with fp32 accumulate (validated R9)
__device__ __forceinline__ void mma_f16(float* d, const uint32_t* a,
                                        uint32_t b0, uint32_t b1) {
    asm volatile(
        "mma.sync.aligned.m16n8k16.row.col.f32.f16.f16.f32 "
        "{%0,%1,%2,%3}, {%4,%5,%6,%7}, {%8,%9}, {%0,%1,%2,%3};"
        : "+f"(d[0]), "+f"(d[1]), "+f"(d[2]), "+f"(d[3])
        : "r"(a[0]), "r"(a[1]), "r"(a[2]), "r"(a[3]), "r"(b0), "r"(b1));
}

// ---------------------------------------------------------------------------
// Kernel 1: QKV projection via mma.sync tf32; outputs fp16. (validated R7-R9)
// Grid (128 row-tiles, 3 chunks). chunk 0 -> Q (scaled), 1 -> K, 2 -> V^T.
// ---------------------------------------------------------------------------
#define QO_W 16384
#define QO_B 32768
#define SMEM_QKV ((32768 + 128) * 4)

__global__ __launch_bounds__(256, 1) void qkv_mma(const float* __restrict__ X,
                                                  const float* __restrict__ W,
                                                  const float* __restrict__ bias)
{
    extern __shared__ float sm[];
    float* Xs = sm;
    float* Ws = sm + QO_W;
    float* Bs = sm + QO_B;

    const int tid = threadIdx.x;
    const int wid = tid >> 5;
    const int lane = tid & 31;
    const int g = lane >> 2;
    const int tg = lane & 3;
    const int xg = g << 2;
    const int m0 = (wid >> 1) * 32;
    const int n0 = (wid & 1) * 64;
    const int row0 = blockIdx.x * 128;
    const int c = blockIdx.y;

    {
        const float4* Xg = (const float4*)(X + (size_t)row0 * HH);
        #pragma unroll
        for (int i = 0; i < 16; i++) {
            int idx = tid + i * 256;
            int r = idx >> 5;
            int c4 = (idx & 31) << 2;
            float4 v = Xg[idx];
            v.x = to_tf32(v.x); v.y = to_tf32(v.y);
            v.z = to_tf32(v.z); v.w = to_tf32(v.w);
            *(float4*)(Xs + (r << 7) + (c4 ^ ((r & 7) << 2))) = v;
        }
        const float4* Wg = (const float4*)(W + (size_t)c * 128 * HH);
        #pragma unroll
        for (int i = 0; i < 16; i++) {
            int idx = tid + i * 256;
            int r = idx >> 5;
            int c4 = (idx & 31) << 2;
            float4 v = Wg[idx];
            v.x = to_tf32(v.x); v.y = to_tf32(v.y);
            v.z = to_tf32(v.z); v.w = to_tf32(v.w);
            *(float4*)(Ws + (r << 7) + (c4 ^ ((r & 7) << 2))) = v;
        }
        if (tid < 128) Bs[tid] = bias[c * 128 + tid];
    }
    __syncthreads();

    float acc[2][8][4];
    #pragma unroll
    for (int st = 0; st < 2; st++)
        #pragma unroll
        for (int nt = 0; nt < 8; nt++)
            #pragma unroll
            for (int j = 0; j < 4; j++) acc[st][nt][j] = 0.0f;

    const float* XA0 = Xs + ((m0 + g) << 7);
    const float* XA1 = Xs + ((m0 + 8 + g) << 7);
    const float* XA2 = Xs + ((m0 + 16 + g) << 7);
    const float* XA3 = Xs + ((m0 + 24 + g) << 7);

    #pragma unroll 2
    for (int ks = 0; ks < 16; ks++) {
        const int k0 = ks * 8;
        const int c0 = (k0 + tg) ^ xg;
        const int c1 = (k0 + tg + 4) ^ xg;
        uint32_t a0[4], a1[4];
        a0[0] = __float_as_uint(XA0[c0]);
        a0[1] = __float_as_uint(XA1[c0]);
        a0[2] = __float_as_uint(XA0[c1]);
        a0[3] = __float_as_uint(XA1[c1]);
        a1[0] = __float_as_uint(XA2[c0]);
        a1[1] = __float_as_uint(XA3[c0]);
        a1[2] = __float_as_uint(XA2[c1]);
        a1[3] = __float_as_uint(XA3[c1]);
        #pragma unroll
        for (int nt = 0; nt < 8; nt++) {
            const float* Br = Ws + ((n0 + nt * 8 + g) << 7);
            uint32_t b0 = __float_as_uint(Br[c0]);
            uint32_t b1 = __float_as_uint(Br[c1]);
            mma_tf32(acc[0][nt], a0, b0, b1);
            mma_tf32(acc[1][nt], a1, b0, b1);
        }
    }

    if (c == 2) {
        __syncthreads();
        float* St = sm;    // 128 x 130 plain (s rows, h cols)
        #pragma unroll
        for (int st = 0; st < 2; st++) {
            #pragma unroll
            for (int nt = 0; nt < 8; nt++) {
                int col = n0 + nt * 8 + 2 * tg;
                int r0 = m0 + 16 * st + g;
                int r1 = r0 + 8;
                float b0v = Bs[col], b1v = Bs[col + 1];
                St[r0 * 130 + col]     = acc[st][nt][0] + b0v;
                St[r0 * 130 + col + 1] = acc[st][nt][1] + b1v;
                St[r1 * 130 + col]     = acc[st][nt][2] + b0v;
                St[r1 * 130 + col + 1] = acc[st][nt][3] + b1v;
            }
        }
        __syncthreads();
        const int b = row0 >> 12;
        const int sbase = row0 & 4095;
        #pragma unroll 4
        for (int i = 0; i < 64; i++) {
            int idx = tid + i * 256;
            int h = idx >> 7;
            int s = idx & 127;
            g_Vt[((size_t)(b * HH + h)) * SS + sbase + s] = __float2half_rn(St[s * 130 + h]);
        }
    } else {
        __half* dst = (c == 0 ? g_Q : g_K) + (size_t)row0 * HH;
        const float scale = (c == 0) ? 0.08838834764831845f : 1.0f;
        #pragma unroll
        for (int st = 0; st < 2; st++) {
            #pragma unroll
            for (int nt = 0; nt < 8; nt++) {
                int col = n0 + nt * 8 + 2 * tg;
                int r0 = m0 + 16 * st + g;
                int r1 = r0 + 8;
                float b0v = Bs[col], b1v = Bs[col + 1];
                *(__half2*)(dst + (size_t)r0 * HH + col) =
                    __floats2half2_rn((acc[st][nt][0] + b0v) * scale,
                                      (acc[st][nt][1] + b1v) * scale);
                *(__half2*)(dst + (size_t)r1 * HH + col) =
                    __floats2half2_rn((acc[st][nt][2] + b0v) * scale,
                                      (acc[st][nt][3] + b1v) * scale);
            }
        }
    }
}

// ---------------------------------------------------------------------------
// Kernel 2: flash attention, fp16 mma.sync, FUSED S(t) + PV(t-1) per tile.
// 512 threads, 16 warps: m-strip (w>>2)*32, n-quarter w&3.
// Key-tile 128. K double-buffered, V TRIPLE-buffered (PV(t-1) reads V(t-1)
// while staging writes V(t+1)). P single-buffered (strip-bar between fused
// loop reads of P(t-1) and stores of P(t)).
// SMEM u32: Q[8192] K0 K1 V0 V1 V2 P -> 7*8192 u32 = 229376 B.
// Swizzle: u32-col ^ 4*(row&7).
// ---------------------------------------------------------------------------
#define UQ  0
#define UK0 8192
#define UV0 24576
#define UP  49152
#define SMEM_ATTN (57344 * 4)   // 229376 B

__global__ __launch_bounds__(512, 1) void attn_kernel(float* __restrict__ out)
{
    extern __shared__ uint32_t smu[];
    const uint32_t smem_u32 = smem_u32_of(smu);

    const int tid = threadIdx.x;
    const int wid = tid >> 5;
    const int lane = tid & 31;
    const int g = lane >> 2;
    const int tg = lane & 3;
    const int xg = g << 2;
    const int m0 = (wid >> 2) * 32;       // m-strip base (4 strips)
    const int nq = wid & 3;               // n-quarter
    const int n0k = nq * 32;              // S: 32 keys per warp
    const int n0p = nq * 32;              // PV: 32 head dims per warp
    const int strip_bar = 1 + (wid >> 2); // named barrier per strip (128 thr)
    const int b = blockIdx.y;
    const int q0 = blockIdx.x * 128;

    // ---- prologue: stage tile 0 (K,V) ----
    {
        const __half* Kg = g_K + ((size_t)b * SS) * HH;
        const __half* Vg = g_Vt + (size_t)(b * HH) * SS;
        #pragma unroll
        for (int i = 0; i < 4; i++) {
            int idx = tid + i * 512;
            int r = idx >> 4;
            int c4 = (idx & 15) << 2;
            int sw = c4 ^ ((r & 7) << 2);
            cp_async16(smem_u32 + (UK0 + r * 64 + sw) * 4, Kg + r * HH + c4 * 2);
            cp_async16(smem_u32 + (UV0 + r * 64 + sw) * 4, Vg + (size_t)r * SS + c4 * 2);
        }
        CP_COMMIT();
        // Q tile
        const __half* Qg = g_Q + ((size_t)b * SS + q0) * HH;
        #pragma unroll
        for (int i = 0; i < 4; i++) {
            int idx = tid + i * 512;
            int r = idx >> 4;
            int c4 = (idx & 15) << 2;
            int sw = c4 ^ ((r & 7) << 2);
            *(uint4*)(smu + UQ + r * 64 + sw) = *(const uint4*)(Qg + r * HH + c4 * 2);
        }
    }

    float oacc[2][4][4];
    #pragma unroll
    for (int st = 0; st < 2; st++)
        #pragma unroll
        for (int nt = 0; nt < 4; nt++)
            #pragma unroll
            for (int j = 0; j < 4; j++) oacc[st][nt][j] = 0.0f;
    float lsum[4] = {0.0f, 0.0f, 0.0f, 0.0f};

    // Fragment row pointers (all rows == g mod 8 -> swizzle xor = xg)
    const uint32_t* QA0 = smu + UQ + (m0 + g) * 64;
    const uint32_t* QA1 = smu + UQ + (m0 + 8 + g) * 64;
    const uint32_t* QA2 = smu + UQ + (m0 + 16 + g) * 64;
    const uint32_t* QA3 = smu + UQ + (m0 + 24 + g) * 64;
    uint32_t* PW0 = smu + UP + (m0 + g) * 64;
    uint32_t* PW1 = smu + UP + (m0 + 8 + g) * 64;
    uint32_t* PW2 = smu + UP + (m0 + 16 + g) * 64;
    uint32_t* PW3 = smu + UP + (m0 + 24 + g) * 64;

    for (int t = 0; t < 32; t++) {
        const uint32_t* Kb = smu + UK0 + (t & 1) * 8192;

        CP_WAIT0();
        __syncthreads();   // K(t),V(t) visible; all prior reads of reused bufs done

        // Prefetch tile t+1: K -> other K buf, V -> (t+1)%3 buf
        if (t + 1 < 32) {
            const int ok = UK0 + ((t + 1) & 1) * 8192;
            const int ov = UV0 + ((t + 1) % 3) * 8192;
            const __half* Kg = g_K + ((size_t)b * SS + (t + 1) * 128) * HH;
            const __half* Vg = g_Vt + (size_t)(b * HH) * SS + (t + 1) * 128;
            #pragma unroll
            for (int i = 0; i < 4; i++) {
                int idx = tid + i * 512;
                int r = idx >> 4;
                int c4 = (idx & 15) << 2;
                int sw = c4 ^ ((r & 7) << 2);
                cp_async16(smem_u32 + (ok + r * 64 + sw) * 4, Kg + r * HH + c4 * 2);
                cp_async16(smem_u32 + (ov + r * 64 + sw) * 4, Vg + (size_t)r * SS + c4 * 2);
            }
            CP_COMMIT();
        }

        // --- FUSED: S(t) [Q x K(t)] + PV(t-1) [P(t-1) x V(t-1)] ---
        float sacc[2][4][4];
        #pragma unroll
        for (int st = 0; st < 2; st++)
            #pragma unroll
            for (int nt = 0; nt < 4; nt++)
                #pragma unroll
                for (int j = 0; j < 4; j++) sacc[st][nt][j] = 0.0f;

        if (t > 0) {
            const uint32_t* Vb = smu + UV0 + ((t - 1) % 3) * 8192;
            #pragma unroll 2
            for (int ks = 0; ks < 8; ks++) {
                const int c0 = (ks * 8 + tg) ^ xg;
                const int c1 = (ks * 8 + tg + 4) ^ xg;
                // S stream
                uint32_t a0[4], a1[4];
                a0[0] = QA0[c0]; a0[1] = QA1[c0]; a0[2] = QA0[c1]; a0[3] = QA1[c1];
                a1[0] = QA2[c0]; a1[1] = QA3[c0]; a1[2] = QA2[c1]; a1[3] = QA3[c1];
                // PV stream (P of tile t-1)
                uint32_t p0[4], p1[4];
                p0[0] = PW0[c0]; p0[1] = PW1[c0]; p0[2] = PW0[c1]; p0[3] = PW1[c1];
                p1[0] = PW2[c0]; p1[1] = PW3[c0]; p1[2] = PW2[c1]; p1[3] = PW3[c1];
                #pragma unroll
                for (int nt = 0; nt < 4; nt++) {
                    const uint32_t* Brk = Kb + (n0k + nt * 8 + g) * 64;
                    uint32_t bk0 = Brk[c0];
                    uint32_t bk1 = Brk[c1];
                    const uint32_t* Brv = Vb + (n0p + nt * 8 + g) * 64;
                    uint32_t bv0 = Brv[c0];
                    uint32_t bv1 = Brv[c1];
                    mma_f16(sacc[0][nt], a0, bk0, bk1);
                    mma_f16(oacc[0][nt], p0, bv0, bv1);
                    mma_f16(sacc[1][nt], a1, bk0, bk1);
                    mma_f16(oacc[1][nt], p1, bv0, bv1);
                }
            }
        } else {
            #pragma unroll 2
            for (int ks = 0; ks < 8; ks++) {
                const int c0 = (ks * 8 + tg) ^ xg;
                const int c1 = (ks * 8 + tg + 4) ^ xg;
                uint32_t a0[4], a1[4];
                a0[0] = QA0[c0]; a0[1] = QA1[c0]; a0[2] = QA0[c1]; a0[3] = QA1[c1];
                a1[0] = QA2[c0]; a1[1] = QA3[c0]; a1[2] = QA2[c1]; a1[3] = QA3[c1];
                #pragma unroll
                for (int nt = 0; nt < 4; nt++) {
                    const uint32_t* Brk = Kb + (n0k + nt * 8 + g) * 64;
                    uint32_t bk0 = Brk[c0];
                    uint32_t bk1 = Brk[c1];
                    mma_f16(sacc[0][nt], a0, bk0, bk1);
                    mma_f16(sacc[1][nt], a1, bk0, bk1);
                }
            }
        }

        // Strip barrier: siblings done reading P(t-1) before P(t) overwrites it
        asm volatile("bar.sync %0, 128;" :: "r"(strip_bar) : "memory");

        // --- exp + partial row sums + write P(t) (fp16 pairs, swizzled) ---
        {
            float ps0 = 0.0f, ps1 = 0.0f, ps2 = 0.0f, ps3 = 0.0f;
            #pragma unroll
            for (int nt = 0; nt < 4; nt++) {
                int cp = (nq * 16 + nt * 4 + tg) ^ xg;
                float e0 = __expf(sacc[0][nt][0]);
                float e1 = __expf(sacc[0][nt][1]);
                float e2 = __expf(sacc[0][nt][2]);
                float e3 = __expf(sacc[0][nt][3]);
                ps0 += e0 + e1; ps1 += e2 + e3;
                __half2 h01 = __floats2half2_rn(e0, e1);
                __half2 h23 = __floats2half2_rn(e2, e3);
                PW0[cp] = *reinterpret_cast<uint32_t*>(&h01);
                PW1[cp] = *reinterpret_cast<uint32_t*>(&h23);
                float f0 = __expf(sacc[1][nt][0]);
                float f1 = __expf(sacc[1][nt][1]);
                float f2 = __expf(sacc[1][nt][2]);
                float f3 = __expf(sacc[1][nt][3]);
                ps2 += f0 + f1; ps3 += f2 + f3;
                __half2 g01 = __floats2half2_rn(f0, f1);
                __half2 g23 = __floats2half2_rn(f2, f3);
                PW2[cp] = *reinterpret_cast<uint32_t*>(&g01);
                PW3[cp] = *reinterpret_cast<uint32_t*>(&g23);
            }
            ps0 += __shfl_xor_sync(0xffffffffu, ps0, 1);
            ps0 += __shfl_xor_sync(0xffffffffu, ps0, 2);
            ps1 += __shfl_xor_sync(0xffffffffu, ps1, 1);
            ps1 += __shfl_xor_sync(0xffffffffu, ps1, 2);
            ps2 += __shfl_xor_sync(0xffffffffu, ps2, 1);
            ps2 += __shfl_xor_sync(0xffffffffu, ps2, 2);
            ps3 += __shfl_xor_sync(0xffffffffu, ps3, 1);
            ps3 += __shfl_xor_sync(0xffffffffu, ps3, 2);
            lsum[0] += ps0; lsum[1] += ps1; lsum[2] += ps2; lsum[3] += ps3;
        }
    }

    // --- Drain: PV(31) standalone ---
    __syncthreads();   // all P(31) stores visible
    {
        const uint32_t* Vb = smu + UV0 + (31 % 3) * 8192;
        #pragma unroll 2
        for (int ks = 0; ks < 8; ks++) {
            const int c0 = (ks * 8 + tg) ^ xg;
            const int c1 = (ks * 8 + tg + 4) ^ xg;
            uint32_t p0[4], p1[4];
            p0[0] = PW0[c0]; p0[1] = PW1[c0]; p0[2] = PW0[c1]; p0[3] = PW1[c1];
            p1[0] = PW2[c0]; p1[1] = PW3[c0]; p1[2] = PW2[c1]; p1[3] = PW3[c1];
            #pragma unroll
            for (int nt = 0; nt < 4; nt++) {
                const uint32_t* Brv = Vb + (n0p + nt * 8 + g) * 64;
                uint32_t bv0 = Brv[c0];
                uint32_t bv1 = Brv[c1];
                mma_f16(oacc[0][nt], p0, bv0, bv1);
                mma_f16(oacc[1][nt], p1, bv0, bv1);
            }
        }
    }

    // --- Combine per-quarter row sums via smem (reuse P region as f32) ---
    __syncthreads();
    {
        float* LS = (float*)(smu + UP) + nq * 128;
        if (tg == 0) {
            LS[m0 + g] = lsum[0];
            LS[m0 + 8 + g] = lsum[1];
            LS[m0 + 16 + g] = lsum[2];
            LS[m0 + 24 + g] = lsum[3];
        }
    }
    __syncthreads();

    // --- Epilogue: O / l -> gmem (f32 out) ---
    {
        const float* LS = (const float*)(smu + UP);
        float* og = out + ((size_t)(b * SS) + q0) * HH + n0p;
        #pragma unroll
        for (int st = 0; st < 2; st++) {
            int r0 = m0 + 16 * st + g;
            int r1 = r0 + 8;
            float inv0 = 1.0f / (LS[r0] + LS[128 + r0] + LS[256 + r0] + LS[384 + r0]);
            float inv1 = 1.0f / (LS[r1] + LS[128 + r1] + LS[256 + r1] + LS[384 + r1]);
            float* o0 = og + (size_t)r0 * HH;
            float* o1 = og + (size_t)r1 * HH;
            #pragma unroll
            for (int nt = 0; nt < 4; nt++) {
                int col = nt * 8 + 2 * tg;
                *(float2*)(o0 + col) =
                    make_float2(oacc[st][nt][0] * inv0, oacc[st][nt][1] * inv0);
                *(float2*)(o1 + col) =
                    make_float2(oacc[st][nt][2] * inv1, oacc[st][nt][3] * inv1);
            }
        }
    }
}

// ---------------------------------------------------------------------------
extern "C" void kernel_launch(void* const* d_in, const int* in_sizes, int n_in,
                              void* d_out, int out_size)
{
    const float* X    = (const float*)d_in[0];   // [4,4096,128]
    const float* W    = (const float*)d_in[1];   // [384,128]
    const float* bias = (const float*)d_in[2];   // [384]
    float* out = (float*)d_out;                  // [4,4096,128]

    cudaFuncSetAttribute(qkv_mma, cudaFuncAttributeMaxDynamicSharedMemorySize, SMEM_QKV);
    cudaFuncSetAttribute(attn_kernel, cudaFuncAttributeMaxDynamicSharedMemorySize, SMEM_ATTN);

    qkv_mma<<<dim3(128, 3), 256, SMEM_QKV>>>(X, W, bias);
    attn_kernel<<<dim3(SS / 128, BB), 512, SMEM_ATTN>>>(out);
}

// round 11
// speedup vs baseline: 1.1491x; 1.1491x over previous
#include <cuda_runtime.h>
#include <cuda_fp16.h>
#include <math.h>
#include <stdint.h>

#define BB 4
#define SS 4096
#define HH 128
#define ROWS_TOTAL (BB * SS)

// Scratch (allocation-free path). Q pre-scaled by log2(e)/sqrt(H). All fp16.
// V stored transposed: g_Vt[b][h][s].
__device__ __half g_Q[ROWS_TOTAL * HH];
__device__ __half g_K[ROWS_TOTAL * HH];
__device__ __half g_Vt[BB * HH * SS];

__device__ __forceinline__ float to_tf32(float x) {
    uint32_t u;
    asm("cvt.rna.tf32.f32 %0, %1;" : "=r"(u) : "f"(x));
    return __uint_as_float(u);
}

__device__ __forceinline__ float ex2f(float x) {
    float y;
    asm("ex2.approx.ftz.f32 %0, %1;" : "=f"(y) : "f"(x));
    return y;
}

__device__ __forceinline__ uint32_t smem_u32_of(const void* p) {
    uint32_t a;
    asm("{ .reg .u64 t; cvta.to.shared.u64 t, %1; cvt.u32.u64 %0, t; }" : "=r"(a) : "l"(p));
    return a;
}

__device__ __forceinline__ void cp_async16(uint32_t dst, const void* src) {
    asm volatile("cp.async.cg.shared.global [%0], [%1], 16;" :: "r"(dst), "l"(src));
}
#define CP_COMMIT() asm volatile("cp.async.commit_group;" ::: "memory")
#define CP_WAIT0()  asm volatile("cp.async.wait_group 0;" ::: "memory")

// ldmatrix x4: 4 8x8 b16 matrices, lanes 8m..8m+7 address matrix m's rows.
__device__ __forceinline__ void ldsm_x4(uint32_t* r, uint32_t addr) {
    asm volatile("ldmatrix.sync.aligned.m8n8.x4.shared.b16 {%0,%1,%2,%3}, [%4];"
        : "=r"(r[0]), "=r"(r[1]), "=r"(r[2]), "=r"(r[3]) : "r"(addr));
}

// tf32 m16n8k8 (for QKV projection; validated R3-R10)
__device__ __forceinline__ void mma_tf32(float* d, const uint32_t* a,
                                         uint32_t b0, uint32_t b1) {
    asm volatile(
        "mma.sync.aligned.m16n8k8.row.col.f32.tf32.tf32.f32 "
        "{%0,%1,%2,%3}, {%4,%5,%6,%7}, {%8,%9}, {%0,%1,%2,%3};"
        : "+f"(d[0]), "+f"(d[1]), "+f"(d[2]), "+f"(d[3])
        : "r"(a[0]), "r"(a[1]), "r"(a[2]), "r"(a[3]), "r"(b0), "r"(b1));
}

// fp16 m16n8k16 with fp32 accumulate (validated R9/R10)
__device__ __forceinline__ void mma_f16(float* d, const uint32_t* a,
                                        uint32_t b0, uint32_t b1) {
    asm volatile(
        "mma.sync.aligned.m16n8k16.row.col.f32.f16.f16.f32 "
        "{%0,%1,%2,%3}, {%4,%5,%6,%7}, {%8,%9}, {%0,%1,%2,%3};"
        : "+f"(d[0]), "+f"(d[1]), "+f"(d[2]), "+f"(d[3])
        : "r"(a[0]), "r"(a[1]), "r"(a[2]), "r"(a[3]), "r"(b0), "r"(b1));
}

// ---------------------------------------------------------------------------
// Kernel 1: QKV projection via mma.sync tf32; outputs fp16. (validated R7-R10)
// Q scaled by log2(e)/sqrt(128) so attention scores land in log2 domain.
// ---------------------------------------------------------------------------
#define QO_W 16384
#define QO_B 32768
#define SMEM_QKV ((32768 + 128) * 4)

__global__ __launch_bounds__(256, 1) void qkv_mma(const float* __restrict__ X,
                                                  const float* __restrict__ W,
                                                  const float* __restrict__ bias)
{
    extern __shared__ float sm[];
    float* Xs = sm;
    float* Ws = sm + QO_W;
    float* Bs = sm + QO_B;

    const int tid = threadIdx.x;
    const int wid = tid >> 5;
    const int lane = tid & 31;
    const int g = lane >> 2;
    const int tg = lane & 3;
    const int xg = g << 2;
    const int m0 = (wid >> 1) * 32;
    const int n0 = (wid & 1) * 64;
    const int row0 = blockIdx.x * 128;
    const int c = blockIdx.y;

    {
        const float4* Xg = (const float4*)(X + (size_t)row0 * HH);
        #pragma unroll
        for (int i = 0; i < 16; i++) {
            int idx = tid + i * 256;
            int r = idx >> 5;
            int c4 = (idx & 31) << 2;
            float4 v = Xg[idx];
            v.x = to_tf32(v.x); v.y = to_tf32(v.y);
            v.z = to_tf32(v.z); v.w = to_tf32(v.w);
            *(float4*)(Xs + (r << 7) + (c4 ^ ((r & 7) << 2))) = v;
        }
        const float4* Wg = (const float4*)(W + (size_t)c * 128 * HH);
        #pragma unroll
        for (int i = 0; i < 16; i++) {
            int idx = tid + i * 256;
            int r = idx >> 5;
            int c4 = (idx & 31) << 2;
            float4 v = Wg[idx];
            v.x = to_tf32(v.x); v.y = to_tf32(v.y);
            v.z = to_tf32(v.z); v.w = to_tf32(v.w);
            *(float4*)(Ws + (r << 7) + (c4 ^ ((r & 7) << 2))) = v;
        }
        if (tid < 128) Bs[tid] = bias[c * 128 + tid];
    }
    __syncthreads();

    float acc[2][8][4];
    #pragma unroll
    for (int st = 0; st < 2; st++)
        #pragma unroll
        for (int nt = 0; nt < 8; nt++)
            #pragma unroll
            for (int j = 0; j < 4; j++) acc[st][nt][j] = 0.0f;

    const float* XA0 = Xs + ((m0 + g) << 7);
    const float* XA1 = Xs + ((m0 + 8 + g) << 7);
    const float* XA2 = Xs + ((m0 + 16 + g) << 7);
    const float* XA3 = Xs + ((m0 + 24 + g) << 7);

    #pragma unroll 2
    for (int ks = 0; ks < 16; ks++) {
        const int k0 = ks * 8;
        const int c0 = (k0 + tg) ^ xg;
        const int c1 = (k0 + tg + 4) ^ xg;
        uint32_t a0[4], a1[4];
        a0[0] = __float_as_uint(XA0[c0]);
        a0[1] = __float_as_uint(XA1[c0]);
        a0[2] = __float_as_uint(XA0[c1]);
        a0[3] = __float_as_uint(XA1[c1]);
        a1[0] = __float_as_uint(XA2[c0]);
        a1[1] = __float_as_uint(XA3[c0]);
        a1[2] = __float_as_uint(XA2[c1]);
        a1[3] = __float_as_uint(XA3[c1]);
        #pragma unroll
        for (int nt = 0; nt < 8; nt++) {
            const float* Br = Ws + ((n0 + nt * 8 + g) << 7);
            uint32_t b0 = __float_as_uint(Br[c0]);
            uint32_t b1 = __float_as_uint(Br[c1]);
            mma_tf32(acc[0][nt], a0, b0, b1);
            mma_tf32(acc[1][nt], a1, b0, b1);
        }
    }

    if (c == 2) {
        __syncthreads();
        float* St = sm;    // 128 x 130 plain (s rows, h cols)
        #pragma unroll
        for (int st = 0; st < 2; st++) {
            #pragma unroll
            for (int nt = 0; nt < 8; nt++) {
                int col = n0 + nt * 8 + 2 * tg;
                int r0 = m0 + 16 * st + g;
                int r1 = r0 + 8;
                float b0v = Bs[col], b1v = Bs[col + 1];
                St[r0 * 130 + col]     = acc[st][nt][0] + b0v;
                St[r0 * 130 + col + 1] = acc[st][nt][1] + b1v;
                St[r1 * 130 + col]     = acc[st][nt][2] + b0v;
                St[r1 * 130 + col + 1] = acc[st][nt][3] + b1v;
            }
        }
        __syncthreads();
        const int b = row0 >> 12;
        const int sbase = row0 & 4095;
        #pragma unroll 4
        for (int i = 0; i < 64; i++) {
            int idx = tid + i * 256;
            int h = idx >> 7;
            int s = idx & 127;
            g_Vt[((size_t)(b * HH + h)) * SS + sbase + s] = __float2half_rn(St[s * 130 + h]);
        }
    } else {
        __half* dst = (c == 0 ? g_Q : g_K) + (size_t)row0 * HH;
        // Q scale folds 1/sqrt(128) AND log2(e): exp(x) = 2^(x*log2e)
        const float scale = (c == 0)
            ? (0.08838834764831845f * 1.4426950408889634f) : 1.0f;
        #pragma unroll
        for (int st = 0; st < 2; st++) {
            #pragma unroll
            for (int nt = 0; nt < 8; nt++) {
                int col = n0 + nt * 8 + 2 * tg;
                int r0 = m0 + 16 * st + g;
                int r1 = r0 + 8;
                float b0v = Bs[col], b1v = Bs[col + 1];
                *(__half2*)(dst + (size_t)r0 * HH + col) =
                    __floats2half2_rn((acc[st][nt][0] + b0v) * scale,
                                      (acc[st][nt][1] + b1v) * scale);
                *(__half2*)(dst + (size_t)r1 * HH + col) =
                    __floats2half2_rn((acc[st][nt][2] + b0v) * scale,
                                      (acc[st][nt][3] + b1v) * scale);
            }
        }
    }
}

// ---------------------------------------------------------------------------
// Kernel 2: flash attention, fp16 mma.sync + ldmatrix.x4 fragment loads.
// Fused S(t)+PV(t-1). 512 threads, 16 warps: m-strip (w>>2)*32, n-quarter w&3.
// K double-buffered, V triple-buffered, P single-buffered.
// SMEM u32: Q[8192] K0 K1 V0 V1 V2 P -> 229376 B. Swizzle: u32col ^ 4*(row&7).
// ---------------------------------------------------------------------------
#define UQ  0
#define UK0 8192
#define UV0 24576
#define UP  49152
#define SMEM_ATTN (57344 * 4)   // 229376 B

__global__ __launch_bounds__(512, 1) void attn_kernel(float* __restrict__ out)
{
    extern __shared__ uint32_t smu[];
    const uint32_t smem_u32 = smem_u32_of(smu);

    const int tid = threadIdx.x;
    const int wid = tid >> 5;
    const int lane = tid & 31;
    const int g = lane >> 2;
    const int tg = lane & 3;
    const int xg = g << 2;
    const int m0 = (wid >> 2) * 32;       // m-strip base (4 strips)
    const int nq = wid & 3;               // n-quarter
    const int n0 = nq * 32;               // keys (S) / head dims (PV)
    const int strip_bar = 1 + (wid >> 2); // named barrier per strip (128 thr)
    const int b = blockIdx.y;
    const int q0 = blockIdx.x * 128;

    // ---- ldmatrix per-lane address constants ----
    // Swizzled element (row, u32col) lives at u32 index row*64 + (u32col ^ 4*(row&7)).
    // u32col(ks) for a fragment = ks*8 + d (+k-half), d in {0,4}. Decompose the XOR:
    // (ks*8 + d) ^ 4j = ((ks*8) ^ (4j & 24)) + (d ^ (4j & 4)).
    const int j = lane & 7;
    const int mat = lane >> 3;
    const uint32_t xhi4 = (uint32_t)((4 * j) & 24) << 2;             // byte-scaled
    // A-type (Q/P: 16 rows x k16): mat0 rows+0-7 klo, mat1 rows+8-15 klo,
    //                              mat2 rows+0-7 khi, mat3 rows+8-15 khi
    const int rowA = j + 8 * (mat & 1);
    const uint32_t xloA = 16u * (((mat >> 1) ^ j) & 1);
    // B-type (K/V: mat0 rows+0-7 klo, mat1 rows+0-7 khi, mat2 rows+8-15 klo, mat3 khi)
    const int rowB = j + 8 * (mat >> 1);
    const uint32_t xloB = 16u * (((mat & 1) ^ j) & 1);

    const uint32_t qBase   = smem_u32 + UQ  * 4 + (uint32_t)(m0 + rowA) * 256 + xloA;
    const uint32_t pBase   = smem_u32 + UP  * 4 + (uint32_t)(m0 + rowA) * 256 + xloA;
    const uint32_t kCommon = smem_u32 + UK0 * 4 + (uint32_t)(n0 + rowB) * 256 + xloB;
    const uint32_t vCommon = smem_u32 + UV0 * 4 + (uint32_t)(n0 + rowB) * 256 + xloB;

    // ---- prologue: stage tile 0 (K,V) ----
    {
        const __half* Kg = g_K + ((size_t)b * SS) * HH;
        const __half* Vg = g_Vt + (size_t)(b * HH) * SS;
        #pragma unroll
        for (int i = 0; i < 4; i++) {
            int idx = tid + i * 512;
            int r = idx >> 4;
            int c4 = (idx & 15) << 2;
            int sw = c4 ^ ((r & 7) << 2);
            cp_async16(smem_u32 + (UK0 + r * 64 + sw) * 4, Kg + r * HH + c4 * 2);
            cp_async16(smem_u32 + (UV0 + r * 64 + sw) * 4, Vg + (size_t)r * SS + c4 * 2);
        }
        CP_COMMIT();
        // Q tile
        const __half* Qg = g_Q + ((size_t)b * SS + q0) * HH;
        #pragma unroll
        for (int i = 0; i < 4; i++) {
            int idx = tid + i * 512;
            int r = idx >> 4;
            int c4 = (idx & 15) << 2;
            int sw = c4 ^ ((r & 7) << 2);
            *(uint4*)(smu + UQ + r * 64 + sw) = *(const uint4*)(Qg + r * HH + c4 * 2);
        }
    }

    float oacc[2][4][4];
    #pragma unroll
    for (int st = 0; st < 2; st++)
        #pragma unroll
        for (int nt = 0; nt < 4; nt++)
            #pragma unroll
            for (int jj = 0; jj < 4; jj++) oacc[st][nt][jj] = 0.0f;
    float lsum[4] = {0.0f, 0.0f, 0.0f, 0.0f};

    // P store pointers (rows m0+{0,8,16,24}+g, all == g mod 8 -> xor = xg)
    uint32_t* PW0 = smu + UP + (m0 + g) * 64;
    uint32_t* PW1 = smu + UP + (m0 + 8 + g) * 64;
    uint32_t* PW2 = smu + UP + (m0 + 16 + g) * 64;
    uint32_t* PW3 = smu + UP + (m0 + 24 + g) * 64;

    for (int t = 0; t < 32; t++) {
        const uint32_t kBase = kCommon + (uint32_t)(t & 1) * 32768u;

        CP_WAIT0();
        __syncthreads();   // K(t),V(t) visible; all prior reads of reused bufs done

        // Prefetch tile t+1: K -> other K buf, V -> (t+1)%3 buf
        if (t + 1 < 32) {
            const int ok = UK0 + ((t + 1) & 1) * 8192;
            const int ov = UV0 + ((t + 1) % 3) * 8192;
            const __half* Kg = g_K + ((size_t)b * SS + (t + 1) * 128) * HH;
            const __half* Vg = g_Vt + (size_t)(b * HH) * SS + (t + 1) * 128;
            #pragma unroll
            for (int i = 0; i < 4; i++) {
                int idx = tid + i * 512;
                int r = idx >> 4;
                int c4 = (idx & 15) << 2;
                int sw = c4 ^ ((r & 7) << 2);
                cp_async16(smem_u32 + (ok + r * 64 + sw) * 4, Kg + r * HH + c4 * 2);
                cp_async16(smem_u32 + (ov + r * 64 + sw) * 4, Vg + (size_t)r * SS + c4 * 2);
            }
            CP_COMMIT();
        }

        // --- FUSED: S(t) [Q x K(t)] + PV(t-1) [P(t-1) x V(t-1)], ldmatrix loads ---
        float sacc[2][4][4];
        #pragma unroll
        for (int st = 0; st < 2; st++)
            #pragma unroll
            for (int nt = 0; nt < 4; nt++)
                #pragma unroll
                for (int jj = 0; jj < 4; jj++) sacc[st][nt][jj] = 0.0f;

        if (t > 0) {
            const uint32_t vBase = vCommon + (uint32_t)((t - 1) % 3) * 32768u;
            #pragma unroll
            for (int ks = 0; ks < 8; ks++) {
                const uint32_t col4 = ((uint32_t)(ks * 32)) ^ xhi4;
                uint32_t qa0[4], qa1[4], bk[4], bk2[4];
                uint32_t pa0[4], pa1[4], bv[4], bv2[4];
                ldsm_x4(qa0, qBase + col4);
                ldsm_x4(qa1, qBase + col4 + 4096);
                ldsm_x4(bk,  kBase + col4);
                ldsm_x4(bk2, kBase + col4 + 4096);
                ldsm_x4(pa0, pBase + col4);
                ldsm_x4(pa1, pBase + col4 + 4096);
                ldsm_x4(bv,  vBase + col4);
                ldsm_x4(bv2, vBase + col4 + 4096);
                mma_f16(sacc[0][0], qa0, bk[0],  bk[1]);
                mma_f16(oacc[0][0], pa0, bv[0],  bv[1]);
                mma_f16(sacc[1][0], qa1, bk[0],  bk[1]);
                mma_f16(oacc[1][0], pa1, bv[0],  bv[1]);
                mma_f16(sacc[0][1], qa0, bk[2],  bk[3]);
                mma_f16(oacc[0][1], pa0, bv[2],  bv[3]);
                mma_f16(sacc[1][1], qa1, bk[2],  bk[3]);
                mma_f16(oacc[1][1], pa1, bv[2],  bv[3]);
                mma_f16(sacc[0][2], qa0, bk2[0], bk2[1]);
                mma_f16(oacc[0][2], pa0, bv2[0], bv2[1]);
                mma_f16(sacc[1][2], qa1, bk2[0], bk2[1]);
                mma_f16(oacc[1][2], pa1, bv2[0], bv2[1]);
                mma_f16(sacc[0][3], qa0, bk2[2], bk2[3]);
                mma_f16(oacc[0][3], pa0, bv2[2], bv2[3]);
                mma_f16(sacc[1][3], qa1, bk2[2], bk2[3]);
                mma_f16(oacc[1][3], pa1, bv2[2], bv2[3]);
            }
        } else {
            #pragma unroll
            for (int ks = 0; ks < 8; ks++) {
                const uint32_t col4 = ((uint32_t)(ks * 32)) ^ xhi4;
                uint32_t qa0[4], qa1[4], bk[4], bk2[4];
                ldsm_x4(qa0, qBase + col4);
                ldsm_x4(qa1, qBase + col4 + 4096);
                ldsm_x4(bk,  kBase + col4);
                ldsm_x4(bk2, kBase + col4 + 4096);
                mma_f16(sacc[0][0], qa0, bk[0],  bk[1]);
                mma_f16(sacc[1][0], qa1, bk[0],  bk[1]);
                mma_f16(sacc[0][1], qa0, bk[2],  bk[3]);
                mma_f16(sacc[1][1], qa1, bk[2],  bk[3]);
                mma_f16(sacc[0][2], qa0, bk2[0], bk2[1]);
                mma_f16(sacc[1][2], qa1, bk2[0], bk2[1]);
                mma_f16(sacc[0][3], qa0, bk2[2], bk2[3]);
                mma_f16(sacc[1][3], qa1, bk2[2], bk2[3]);
            }
        }

        // --- exp (2^s, scores pre-scaled by log2e) to registers + psums ---
        uint32_t pk[4][4];
        {
            float ps0 = 0.0f, ps1 = 0.0f, ps2 = 0.0f, ps3 = 0.0f;
            #pragma unroll
            for (int nt = 0; nt < 4; nt++) {
                float e0 = ex2f(sacc[0][nt][0]);
                float e1 = ex2f(sacc[0][nt][1]);
                float e2 = ex2f(sacc[0][nt][2]);
                float e3 = ex2f(sacc[0][nt][3]);
                ps0 += e0 + e1; ps1 += e2 + e3;
                __half2 h01 = __floats2half2_rn(e0, e1);
                __half2 h23 = __floats2half2_rn(e2, e3);
                pk[nt][0] = *reinterpret_cast<uint32_t*>(&h01);
                pk[nt][1] = *reinterpret_cast<uint32_t*>(&h23);
                float f0 = ex2f(sacc[1][nt][0]);
                float f1 = ex2f(sacc[1][nt][1]);
                float f2 = ex2f(sacc[1][nt][2]);
                float f3 = ex2f(sacc[1][nt][3]);
                ps2 += f0 + f1; ps3 += f2 + f3;
                __half2 g01 = __floats2half2_rn(f0, f1);
                __half2 g23 = __floats2half2_rn(f2, f3);
                pk[nt][2] = *reinterpret_cast<uint32_t*>(&g01);
                pk[nt][3] = *reinterpret_cast<uint32_t*>(&g23);
            }
            ps0 += __shfl_xor_sync(0xffffffffu, ps0, 1);
            ps0 += __shfl_xor_sync(0xffffffffu, ps0, 2);
            ps1 += __shfl_xor_sync(0xffffffffu, ps1, 1);
            ps1 += __shfl_xor_sync(0xffffffffu, ps1, 2);
            ps2 += __shfl_xor_sync(0xffffffffu, ps2, 1);
            ps2 += __shfl_xor_sync(0xffffffffu, ps2, 2);
            ps3 += __shfl_xor_sync(0xffffffffu, ps3, 1);
            ps3 += __shfl_xor_sync(0xffffffffu, ps3, 2);
            lsum[0] += ps0; lsum[1] += ps1; lsum[2] += ps2; lsum[3] += ps3;
        }

        // Strip barrier: siblings done reading P(t-1) before P(t) overwrites it
        asm volatile("bar.sync %0, 128;" :: "r"(strip_bar) : "memory");

        // --- store P(t) (fp16 pairs, swizzled) ---
        #pragma unroll
        for (int nt = 0; nt < 4; nt++) {
            int cp = (nq * 16 + nt * 4 + tg) ^ xg;
            PW0[cp] = pk[nt][0];
            PW1[cp] = pk[nt][1];
            PW2[cp] = pk[nt][2];
            PW3[cp] = pk[nt][3];
        }
    }

    // --- Drain: PV(31) standalone (ldmatrix) ---
    __syncthreads();   // all P(31) stores visible
    {
        const uint32_t vBase = vCommon + (uint32_t)(31 % 3) * 32768u;
        #pragma unroll
        for (int ks = 0; ks < 8; ks++) {
            const uint32_t col4 = ((uint32_t)(ks * 32)) ^ xhi4;
            uint32_t pa0[4], pa1[4], bv[4], bv2[4];
            ldsm_x4(pa0, pBase + col4);
            ldsm_x4(pa1, pBase + col4 + 4096);
            ldsm_x4(bv,  vBase + col4);
            ldsm_x4(bv2, vBase + col4 + 4096);
            mma_f16(oacc[0][0], pa0, bv[0],  bv[1]);
            mma_f16(oacc[1][0], pa1, bv[0],  bv[1]);
            mma_f16(oacc[0][1], pa0, bv[2],  bv[3]);
            mma_f16(oacc[1][1], pa1, bv[2],  bv[3]);
            mma_f16(oacc[0][2], pa0, bv2[0], bv2[1]);
            mma_f16(oacc[1][2], pa1, bv2[0], bv2[1]);
            mma_f16(oacc[0][3], pa0, bv2[2], bv2[3]);
            mma_f16(oacc[1][3], pa1, bv2[2], bv2[3]);
        }
    }

    // --- Combine per-quarter row sums via smem (reuse P region as f32) ---
    __syncthreads();
    {
        float* LS = (float*)(smu + UP) + nq * 128;
        if (tg == 0) {
            LS[m0 + g] = lsum[0];
            LS[m0 + 8 + g] = lsum[1];
            LS[m0 + 16 + g] = lsum[2];
            LS[m0 + 24 + g] = lsum[3];
        }
    }
    __syncthreads();

    // --- Epilogue: O / l -> gmem (f32 out) ---
    {
        const float* LS = (const float*)(smu + UP);
        float* og = out + ((size_t)(b * SS) + q0) * HH + n0;
        #pragma unroll
        for (int st = 0; st < 2; st++) {
            int r0 = m0 + 16 * st + g;
            int r1 = r0 + 8;
            float inv0 = 1.0f / (LS[r0] + LS[128 + r0] + LS[256 + r0] + LS[384 + r0]);
            float inv1 = 1.0f / (LS[r1] + LS[128 + r1] + LS[256 + r1] + LS[384 + r1]);
            float* o0 = og + (size_t)r0 * HH;
            float* o1 = og + (size_t)r1 * HH;
            #pragma unroll
            for (int nt = 0; nt < 4; nt++) {
                int col = nt * 8 + 2 * tg;
                *(float2*)(o0 + col) =
                    make_float2(oacc[st][nt][0] * inv0, oacc[st][nt][1] * inv0);
                *(float2*)(o1 + col) =
                    make_float2(oacc[st][nt][2] * inv1, oacc[st][nt][3] * inv1);
            }
        }
    }
}

// ---------------------------------------------------------------------------
extern "C" void kernel_launch(void* const* d_in, const int* in_sizes, int n_in,
                              void* d_out, int out_size)
{
    const float* X    = (const float*)d_in[0];   // [4,4096,128]
    const float* W    = (const float*)d_in[1];   // [384,128]
    const float* bias = (const float*)d_in[2];   // [384]
    float* out = (float*)d_out;                  // [4,4096,128]

    cudaFuncSetAttribute(qkv_mma, cudaFuncAttributeMaxDynamicSharedMemorySize, SMEM_QKV);
    cudaFuncSetAttribute(attn_kernel, cudaFuncAttributeMaxDynamicSharedMemorySize, SMEM_ATTN);

    qkv_mma<<<dim3(128, 3), 256, SMEM_QKV>>>(X, W, bias);
    attn_kernel<<<dim3(SS / 128, BB), 512, SMEM_ATTN>>>(out);
}

// round 12
// speedup vs baseline: 1.2092x; 1.0523x over previous
#include <cuda_runtime.h>
#include <cuda_fp16.h>
#include <math.h>
#include <stdint.h>

#define BB 4
#define SS 4096
#define HH 128
#define ROWS_TOTAL (BB * SS)

// Scratch (allocation-free path). Q pre-scaled by log2(e)/sqrt(H). All fp16.
// V stored transposed: g_Vt[b][h][s].
__device__ __half g_Q[ROWS_TOTAL * HH];
__device__ __half g_K[ROWS_TOTAL * HH];
__device__ __half g_Vt[BB * HH * SS];

__device__ __forceinline__ float to_tf32(float x) {
    uint32_t u;
    asm("cvt.rna.tf32.f32 %0, %1;" : "=r"(u) : "f"(x));
    return __uint_as_float(u);
}

__device__ __forceinline__ float ex2f(float x) {
    float y;
    asm("ex2.approx.ftz.f32 %0, %1;" : "=f"(y) : "f"(x));
    return y;
}

__device__ __forceinline__ uint32_t smem_u32_of(const void* p) {
    uint32_t a;
    asm("{ .reg .u64 t; cvta.to.shared.u64 t, %1; cvt.u32.u64 %0, t; }" : "=r"(a) : "l"(p));
    return a;
}

__device__ __forceinline__ void cp_async16(uint32_t dst, const void* src) {
    asm volatile("cp.async.cg.shared.global [%0], [%1], 16;" :: "r"(dst), "l"(src));
}
#define CP_COMMIT() asm volatile("cp.async.commit_group;" ::: "memory")
#define CP_WAIT0()  asm volatile("cp.async.wait_group 0;" ::: "memory")

__device__ __forceinline__ void ldsm_x4(uint32_t* r, uint32_t addr) {
    asm volatile("ldmatrix.sync.aligned.m8n8.x4.shared.b16 {%0,%1,%2,%3}, [%4];"
        : "=r"(r[0]), "=r"(r[1]), "=r"(r[2]), "=r"(r[3]) : "r"(addr));
}

// tf32 m16n8k8 (for QKV projection; validated R3-R11)
__device__ __forceinline__ void mma_tf32(float* d, const uint32_t* a,
                                         uint32_t b0, uint32_t b1) {
    asm volatile(
        "mma.sync.aligned.m16n8k8.row.col.f32.tf32.tf32.f32 "
        "{%0,%1,%2,%3}, {%4,%5,%6,%7}, {%8,%9}, {%0,%1,%2,%3};"
        : "+f"(d[0]), "+f"(d[1]), "+f"(d[2]), "+f"(d[3])
        : "r"(a[0]), "r"(a[1]), "r"(a[2]), "r"(a[3]), "r"(b0), "r"(b1));
}

// fp16 m16n8k16 with fp32 accumulate (validated R9-R11)
__device__ __forceinline__ void mma_f16(float* d, const uint32_t* a,
                                        uint32_t b0, uint32_t b1) {
    asm volatile(
        "mma.sync.aligned.m16n8k16.row.col.f32.f16.f16.f32 "
        "{%0,%1,%2,%3}, {%4,%5,%6,%7}, {%8,%9}, {%0,%1,%2,%3};"
        : "+f"(d[0]), "+f"(d[1]), "+f"(d[2]), "+f"(d[3])
        : "r"(a[0]), "r"(a[1]), "r"(a[2]), "r"(a[3]), "r"(b0), "r"(b1));
}

// ---------------------------------------------------------------------------
// Kernel 1: QKV projection via mma.sync tf32; outputs fp16. (validated R7-R11)
// Q scaled by log2(e)/sqrt(128) so attention scores land in log2 domain.
// ---------------------------------------------------------------------------
#define QO_W 16384
#define QO_B 32768
#define SMEM_QKV ((32768 + 128) * 4)

__global__ __launch_bounds__(256, 1) void qkv_mma(const float* __restrict__ X,
                                                  const float* __restrict__ W,
                                                  const float* __restrict__ bias)
{
    extern __shared__ float sm[];
    float* Xs = sm;
    float* Ws = sm + QO_W;
    float* Bs = sm + QO_B;

    const int tid = threadIdx.x;
    const int wid = tid >> 5;
    const int lane = tid & 31;
    const int g = lane >> 2;
    const int tg = lane & 3;
    const int xg = g << 2;
    const int m0 = (wid >> 1) * 32;
    const int n0 = (wid & 1) * 64;
    const int row0 = blockIdx.x * 128;
    const int c = blockIdx.y;

    {
        const float4* Xg = (const float4*)(X + (size_t)row0 * HH);
        #pragma unroll
        for (int i = 0; i < 16; i++) {
            int idx = tid + i * 256;
            int r = idx >> 5;
            int c4 = (idx & 31) << 2;
            float4 v = Xg[idx];
            v.x = to_tf32(v.x); v.y = to_tf32(v.y);
            v.z = to_tf32(v.z); v.w = to_tf32(v.w);
            *(float4*)(Xs + (r << 7) + (c4 ^ ((r & 7) << 2))) = v;
        }
        const float4* Wg = (const float4*)(W + (size_t)c * 128 * HH);
        #pragma unroll
        for (int i = 0; i < 16; i++) {
            int idx = tid + i * 256;
            int r = idx >> 5;
            int c4 = (idx & 31) << 2;
            float4 v = Wg[idx];
            v.x = to_tf32(v.x); v.y = to_tf32(v.y);
            v.z = to_tf32(v.z); v.w = to_tf32(v.w);
            *(float4*)(Ws + (r << 7) + (c4 ^ ((r & 7) << 2))) = v;
        }
        if (tid < 128) Bs[tid] = bias[c * 128 + tid];
    }
    __syncthreads();

    float acc[2][8][4];
    #pragma unroll
    for (int st = 0; st < 2; st++)
        #pragma unroll
        for (int nt = 0; nt < 8; nt++)
            #pragma unroll
            for (int j = 0; j < 4; j++) acc[st][nt][j] = 0.0f;

    const float* XA0 = Xs + ((m0 + g) << 7);
    const float* XA1 = Xs + ((m0 + 8 + g) << 7);
    const float* XA2 = Xs + ((m0 + 16 + g) << 7);
    const float* XA3 = Xs + ((m0 + 24 + g) << 7);

    #pragma unroll 2
    for (int ks = 0; ks < 16; ks++) {
        const int k0 = ks * 8;
        const int c0 = (k0 + tg) ^ xg;
        const int c1 = (k0 + tg + 4) ^ xg;
        uint32_t a0[4], a1[4];
        a0[0] = __float_as_uint(XA0[c0]);
        a0[1] = __float_as_uint(XA1[c0]);
        a0[2] = __float_as_uint(XA0[c1]);
        a0[3] = __float_as_uint(XA1[c1]);
        a1[0] = __float_as_uint(XA2[c0]);
        a1[1] = __float_as_uint(XA3[c0]);
        a1[2] = __float_as_uint(XA2[c1]);
        a1[3] = __float_as_uint(XA3[c1]);
        #pragma unroll
        for (int nt = 0; nt < 8; nt++) {
            const float* Br = Ws + ((n0 + nt * 8 + g) << 7);
            uint32_t b0 = __float_as_uint(Br[c0]);
            uint32_t b1 = __float_as_uint(Br[c1]);
            mma_tf32(acc[0][nt], a0, b0, b1);
            mma_tf32(acc[1][nt], a1, b0, b1);
        }
    }

    if (c == 2) {
        __syncthreads();
        float* St = sm;    // 128 x 130 plain (s rows, h cols)
        #pragma unroll
        for (int st = 0; st < 2; st++) {
            #pragma unroll
            for (int nt = 0; nt < 8; nt++) {
                int col = n0 + nt * 8 + 2 * tg;
                int r0 = m0 + 16 * st + g;
                int r1 = r0 + 8;
                float b0v = Bs[col], b1v = Bs[col + 1];
                St[r0 * 130 + col]     = acc[st][nt][0] + b0v;
                St[r0 * 130 + col + 1] = acc[st][nt][1] + b1v;
                St[r1 * 130 + col]     = acc[st][nt][2] + b0v;
                St[r1 * 130 + col + 1] = acc[st][nt][3] + b1v;
            }
        }
        __syncthreads();
        const int b = row0 >> 12;
        const int sbase = row0 & 4095;
        #pragma unroll 4
        for (int i = 0; i < 64; i++) {
            int idx = tid + i * 256;
            int h = idx >> 7;
            int s = idx & 127;
            g_Vt[((size_t)(b * HH + h)) * SS + sbase + s] = __float2half_rn(St[s * 130 + h]);
        }
    } else {
        __half* dst = (c == 0 ? g_Q : g_K) + (size_t)row0 * HH;
        const float scale = (c == 0)
            ? (0.08838834764831845f * 1.4426950408889634f) : 1.0f;
        #pragma unroll
        for (int st = 0; st < 2; st++) {
            #pragma unroll
            for (int nt = 0; nt < 8; nt++) {
                int col = n0 + nt * 8 + 2 * tg;
                int r0 = m0 + 16 * st + g;
                int r1 = r0 + 8;
                float b0v = Bs[col], b1v = Bs[col + 1];
                *(__half2*)(dst + (size_t)r0 * HH + col) =
                    __floats2half2_rn((acc[st][nt][0] + b0v) * scale,
                                      (acc[st][nt][1] + b1v) * scale);
                *(__half2*)(dst + (size_t)r1 * HH + col) =
                    __floats2half2_rn((acc[st][nt][2] + b0v) * scale,
                                      (acc[st][nt][3] + b1v) * scale);
            }
        }
    }
}

// ---------------------------------------------------------------------------
// Kernel 2: flash attention, register-resident P (C-frag -> A-frag identity).
// 256 threads, 8 warps = 4 m-strips x 2 key-halves. Warp (s,kh):
//   S  = m32 x n64  (its 64 keys) x k128
//   PV = m32 x h128 x k64 (same keys, partial O; P straight from registers)
// No P smem, no strip barrier. K/V double-buffered cp.async, key-tile 128.
// SMEM u32: Q[8192] K0 K1 V0 V1 = 40960 u32 = 160KB. Swizzle u32col^4*(row&7).
// Epilogue: kh=1 publishes partial O + lsum via smem; kh=0 combines + writes.
// ---------------------------------------------------------------------------
#define UQ  0
#define UK0 8192
#define UV0 24576
#define ULS 16384            // lsum publish area (overlays K1 region, post-loop)
#define SMEM_ATTN (40960 * 4)   // 163840 B

__global__ __launch_bounds__(256, 1) void attn_kernel(float* __restrict__ out)
{
    extern __shared__ uint32_t smu[];
    const uint32_t smem_u32 = smem_u32_of(smu);

    const int tid = threadIdx.x;
    const int wid = tid >> 5;
    const int lane = tid & 31;
    const int g = lane >> 2;
    const int tg = lane & 3;
    const int m0 = (wid >> 1) * 32;   // m-strip
    const int kh = wid & 1;           // key-half
    const int b = blockIdx.y;
    const int q0 = blockIdx.x * 128;

    // ldmatrix per-lane constants (validated R11)
    const int j = lane & 7;
    const int mat = lane >> 3;
    const uint32_t xhi4 = (uint32_t)((4 * j) & 24) << 2;     // byte-scaled
    const int rowA = j + 8 * (mat & 1);
    const uint32_t xloA = 16u * (((mat >> 1) ^ j) & 1);
    const int rowB = j + 8 * (mat >> 1);
    const uint32_t xloB = 16u * (((mat & 1) ^ j) & 1);

    const uint32_t qBase   = smem_u32 + UQ * 4 + (uint32_t)(m0 + rowA) * 256 + xloA;
    const uint32_t kCommon = smem_u32 + UK0 * 4 + (uint32_t)(kh * 64 + rowB) * 256 + xloB;
    const uint32_t vCommon = smem_u32 + UV0 * 4 + (uint32_t)rowB * 256 + xloB;
    const uint32_t vColOff = (uint32_t)(kh * 128);   // byte offset of this half's keys in Vt cols

    // ---- prologue: stage tile 0 (K,V) + Q ----
    {
        const __half* Kg = g_K + ((size_t)b * SS) * HH;
        const __half* Vg = g_Vt + (size_t)(b * HH) * SS;
        #pragma unroll
        for (int i = 0; i < 8; i++) {
            int idx = tid + i * 256;
            int r = idx >> 4;
            int c4 = (idx & 15) << 2;
            int sw = c4 ^ ((r & 7) << 2);
            cp_async16(smem_u32 + (UK0 + r * 64 + sw) * 4, Kg + r * HH + c4 * 2);
            cp_async16(smem_u32 + (UV0 + r * 64 + sw) * 4, Vg + (size_t)r * SS + c4 * 2);
        }
        CP_COMMIT();
        const __half* Qg = g_Q + ((size_t)b * SS + q0) * HH;
        #pragma unroll
        for (int i = 0; i < 8; i++) {
            int idx = tid + i * 256;
            int r = idx >> 4;
            int c4 = (idx & 15) << 2;
            int sw = c4 ^ ((r & 7) << 2);
            *(uint4*)(smu + UQ + r * 64 + sw) = *(const uint4*)(Qg + r * HH + c4 * 2);
        }
    }

    float oacc[2][16][4];   // partial O: m32 x h128 over this warp's keys
    #pragma unroll
    for (int st = 0; st < 2; st++)
        #pragma unroll
        for (int nt = 0; nt < 16; nt++)
            #pragma unroll
            for (int jj = 0; jj < 4; jj++) oacc[st][nt][jj] = 0.0f;
    float lsum[2][2] = {{0.0f, 0.0f}, {0.0f, 0.0f}};   // [st][row-half]

    for (int t = 0; t < 32; t++) {
        const uint32_t kBase = kCommon + (uint32_t)(t & 1) * 32768u;
        const uint32_t vBase = vCommon + (uint32_t)(t & 1) * 32768u;

        CP_WAIT0();
        __syncthreads();   // K(t),V(t) visible; prior reads of reused bufs done

        // Prefetch tile t+1
        if (t + 1 < 32) {
            const int ok = UK0 + ((t + 1) & 1) * 8192;
            const int ov = UV0 + ((t + 1) & 1) * 8192;
            const __half* Kg = g_K + ((size_t)b * SS + (t + 1) * 128) * HH;
            const __half* Vg = g_Vt + (size_t)(b * HH) * SS + (t + 1) * 128;
            #pragma unroll
            for (int i = 0; i < 8; i++) {
                int idx = tid + i * 256;
                int r = idx >> 4;
                int c4 = (idx & 15) << 2;
                int sw = c4 ^ ((r & 7) << 2);
                cp_async16(smem_u32 + (ok + r * 64 + sw) * 4, Kg + r * HH + c4 * 2);
                cp_async16(smem_u32 + (ov + r * 64 + sw) * 4, Vg + (size_t)r * SS + c4 * 2);
            }
            CP_COMMIT();
        }

        // --- S = Q . K^T : m32 x n64 (this warp's 64 keys) x k128 ---
        float sacc[2][8][4];
        #pragma unroll
        for (int st = 0; st < 2; st++)
            #pragma unroll
            for (int nt = 0; nt < 8; nt++)
                #pragma unroll
                for (int jj = 0; jj < 4; jj++) sacc[st][nt][jj] = 0.0f;

        #pragma unroll
        for (int ks = 0; ks < 8; ks++) {
            const uint32_t col4 = ((uint32_t)(ks * 32)) ^ xhi4;
            uint32_t qa0[4], qa1[4];
            ldsm_x4(qa0, qBase + col4);
            ldsm_x4(qa1, qBase + col4 + 4096);
            #pragma unroll
            for (int nb = 0; nb < 4; nb++) {
                uint32_t bk[4];
                ldsm_x4(bk, kBase + (uint32_t)nb * 4096 + col4);
                mma_f16(sacc[0][2 * nb],     qa0, bk[0], bk[1]);
                mma_f16(sacc[1][2 * nb],     qa1, bk[0], bk[1]);
                mma_f16(sacc[0][2 * nb + 1], qa0, bk[2], bk[3]);
                mma_f16(sacc[1][2 * nb + 1], qa1, bk[2], bk[3]);
            }
        }

        // --- exp (2^s) -> P fragments in registers (C-frag == A-frag layout) ---
        uint32_t pf[4][2][4];   // [k-step][m-subtile][a-frag]
        #pragma unroll
        for (int st = 0; st < 2; st++) {
            #pragma unroll
            for (int nt = 0; nt < 8; nt++) {
                float e0 = ex2f(sacc[st][nt][0]);
                float e1 = ex2f(sacc[st][nt][1]);
                float e2 = ex2f(sacc[st][nt][2]);
                float e3 = ex2f(sacc[st][nt][3]);
                lsum[st][0] += e0 + e1;
                lsum[st][1] += e2 + e3;
                __half2 hlo = __floats2half2_rn(e0, e1);
                __half2 hhi = __floats2half2_rn(e2, e3);
                pf[nt >> 1][st][(nt & 1) * 2]     = *reinterpret_cast<uint32_t*>(&hlo);
                pf[nt >> 1][st][(nt & 1) * 2 + 1] = *reinterpret_cast<uint32_t*>(&hhi);
            }
        }

        // --- O += P . V : m32 x h128 x k64 (A straight from registers) ---
        #pragma unroll
        for (int kk = 0; kk < 4; kk++) {
            const uint32_t col4v = (vColOff + (uint32_t)(kk * 32)) ^ xhi4;
            #pragma unroll
            for (int hb = 0; hb < 8; hb++) {
                uint32_t bv[4];
                ldsm_x4(bv, vBase + (uint32_t)hb * 4096 + col4v);
                mma_f16(oacc[0][2 * hb],     pf[kk][0], bv[0], bv[1]);
                mma_f16(oacc[1][2 * hb],     pf[kk][1], bv[0], bv[1]);
                mma_f16(oacc[0][2 * hb + 1], pf[kk][0], bv[2], bv[3]);
                mma_f16(oacc[1][2 * hb + 1], pf[kk][1], bv[2], bv[3]);
            }
        }
    }

    // --- reduce lsum within quads ---
    #pragma unroll
    for (int st = 0; st < 2; st++)
        #pragma unroll
        for (int h = 0; h < 2; h++) {
            lsum[st][h] += __shfl_xor_sync(0xffffffffu, lsum[st][h], 1);
            lsum[st][h] += __shfl_xor_sync(0xffffffffu, lsum[st][h], 2);
        }

    // --- combine key-halves: kh=1 publishes partial O + lsum via smem ---
    __syncthreads();   // staging done with smem; safe to reuse
    {
        float* Ocmb = (float*)smu;                 // 4 strips x 32 x 128 f32 = 64KB
        float* LS = (float*)(smu + ULS);           // 128 f32
        if (kh == 1) {
            float* Obase = Ocmb + (m0 >> 5) * 4096;
            #pragma unroll
            for (int st = 0; st < 2; st++) {
                int r0 = 16 * st + g;
                int r1 = r0 + 8;
                if (tg == 0) {
                    LS[m0 + r0] = lsum[st][0];
                    LS[m0 + r1] = lsum[st][1];
                }
                #pragma unroll
                for (int nt = 0; nt < 16; nt++) {
                    int col = nt * 8 + 2 * tg;
                    *(float2*)(Obase + r0 * 128 + col) =
                        make_float2(oacc[st][nt][0], oacc[st][nt][1]);
                    *(float2*)(Obase + r1 * 128 + col) =
                        make_float2(oacc[st][nt][2], oacc[st][nt][3]);
                }
            }
        }
    }
    __syncthreads();

    // --- epilogue: kh=0 combines, normalizes, writes gmem ---
    if (kh == 0) {
        const float* Ocmb = (const float*)smu + (m0 >> 5) * 4096;
        const float* LS = (const float*)(smu + ULS);
        float* og = out + ((size_t)(b * SS) + q0) * HH;
        #pragma unroll
        for (int st = 0; st < 2; st++) {
            int r0 = 16 * st + g;
            int r1 = r0 + 8;
            float inv0 = 1.0f / (lsum[st][0] + LS[m0 + r0]);
            float inv1 = 1.0f / (lsum[st][1] + LS[m0 + r1]);
            float* o0 = og + (size_t)(m0 + r0) * HH;
            float* o1 = og + (size_t)(m0 + r1) * HH;
            #pragma unroll
            for (int nt = 0; nt < 16; nt++) {
                int col = nt * 8 + 2 * tg;
                float2 p0 = *(const float2*)(Ocmb + r0 * 128 + col);
                float2 p1 = *(const float2*)(Ocmb + r1 * 128 + col);
                *(float2*)(o0 + col) = make_float2((oacc[st][nt][0] + p0.x) * inv0,
                                                   (oacc[st][nt][1] + p0.y) * inv0);
                *(float2*)(o1 + col) = make_float2((oacc[st][nt][2] + p1.x) * inv1,
                                                   (oacc[st][nt][3] + p1.y) * inv1);
            }
        }
    }
}

// ---------------------------------------------------------------------------
extern "C" void kernel_launch(void* const* d_in, const int* in_sizes, int n_in,
                              void* d_out, int out_size)
{
    const float* X    = (const float*)d_in[0];   // [4,4096,128]
    const float* W    = (const float*)d_in[1];   // [384,128]
    const float* bias = (const float*)d_in[2];   // [384]
    float* out = (float*)d_out;                  // [4,4096,128]

    cudaFuncSetAttribute(qkv_mma, cudaFuncAttributeMaxDynamicSharedMemorySize, SMEM_QKV);
    cudaFuncSetAttribute(attn_kernel, cudaFuncAttributeMaxDynamicSharedMemorySize, SMEM_ATTN);

    qkv_mma<<<dim3(128, 3), 256, SMEM_QKV>>>(X, W, bias);
    attn_kernel<<<dim3(SS / 128, BB), 256, SMEM_ATTN>>>(out);
}

// round 13
// speedup vs baseline: 1.2987x; 1.0740x over previous
#include <cuda_runtime.h>
#include <cuda_fp16.h>
#include <math.h>
#include <stdint.h>

#define BB 4
#define SS 4096
#define HH 128
#define ROWS_TOTAL (BB * SS)

// Scratch (allocation-free path). Q pre-scaled by log2(e)/sqrt(H). All fp16.
// V stored transposed: g_Vt[b][h][s].
__device__ __half g_Q[ROWS_TOTAL * HH];
__device__ __half g_K[ROWS_TOTAL * HH];
__device__ __half g_Vt[BB * HH * SS];

__device__ __forceinline__ uint32_t hex2(uint32_t h2) {
    uint32_t y;
    asm("ex2.approx.f16x2 %0, %1;" : "=r"(y) : "r"(h2));
    return y;
}

__device__ __forceinline__ uint32_t smem_u32_of(const void* p) {
    uint32_t a;
    asm("{ .reg .u64 t; cvta.to.shared.u64 t, %1; cvt.u32.u64 %0, t; }" : "=r"(a) : "l"(p));
    return a;
}

__device__ __forceinline__ void cp_async16(uint32_t dst, const void* src) {
    asm volatile("cp.async.cg.shared.global [%0], [%1], 16;" :: "r"(dst), "l"(src));
}
#define CP_COMMIT() asm volatile("cp.async.commit_group;" ::: "memory")
#define CP_WAIT0()  asm volatile("cp.async.wait_group 0;" ::: "memory")

__device__ __forceinline__ void ldsm_x4(uint32_t* r, uint32_t addr) {
    asm volatile("ldmatrix.sync.aligned.m8n8.x4.shared.b16 {%0,%1,%2,%3}, [%4];"
        : "=r"(r[0]), "=r"(r[1]), "=r"(r[2]), "=r"(r[3]) : "r"(addr));
}

// fp16 m16n8k16 with fp32 accumulate (validated R9-R12)
__device__ __forceinline__ void mma_f16(float* d, const uint32_t* a,
                                        uint32_t b0, uint32_t b1) {
    asm volatile(
        "mma.sync.aligned.m16n8k16.row.col.f32.f16.f16.f32 "
        "{%0,%1,%2,%3}, {%4,%5,%6,%7}, {%8,%9}, {%0,%1,%2,%3};"
        : "+f"(d[0]), "+f"(d[1]), "+f"(d[2]), "+f"(d[3])
        : "r"(a[0]), "r"(a[1]), "r"(a[2]), "r"(a[3]), "r"(b0), "r"(b1));
}

#define ONES_H2 0x3C003C00u

// ---------------------------------------------------------------------------
// Kernel 1: QKV projection, fp16 mma.sync + ldmatrix (same machinery as attn).
// Grid (128 row-tiles, 3 chunks). chunk 0 -> Q (scaled by log2e/sqrt(H)),
// 1 -> K, 2 -> V^T. X/W cvt to fp16 on staging.
// SMEM u32: X[8192] W[8192]; St (f32 128x130) overlays; bias at 16640 f32.
// ---------------------------------------------------------------------------
#define QS_X 0
#define QS_W 8192
#define QS_BIAS 16640
#define SMEM_QKV ((16640 + 128) * 4)   // 67072 B

__global__ __launch_bounds__(256, 1) void qkv_f16(const float* __restrict__ X,
                                                  const float* __restrict__ W,
                                                  const float* __restrict__ bias)
{
    extern __shared__ uint32_t smu[];
    const uint32_t smem_u32 = smem_u32_of(smu);
    float* Bs = (float*)(smu + QS_BIAS);

    const int tid = threadIdx.x;
    const int wid = tid >> 5;
    const int lane = tid & 31;
    const int g = lane >> 2;
    const int tg = lane & 3;
    const int m0 = (wid >> 1) * 32;
    const int n0 = (wid & 1) * 64;
    const int row0 = blockIdx.x * 128;
    const int c = blockIdx.y;

    // ldmatrix per-lane constants (validated R11/R12)
    const int j = lane & 7;
    const int mat = lane >> 3;
    const uint32_t xhi4 = (uint32_t)((4 * j) & 24) << 2;
    const int rowA = j + 8 * (mat & 1);
    const uint32_t xloA = 16u * (((mat >> 1) ^ j) & 1);
    const int rowB = j + 8 * (mat >> 1);
    const uint32_t xloB = 16u * (((mat & 1) ^ j) & 1);

    const uint32_t xBase = smem_u32 + QS_X * 4 + (uint32_t)(m0 + rowA) * 256 + xloA;
    const uint32_t wBase = smem_u32 + QS_W * 4 + (uint32_t)(n0 + rowB) * 256 + xloB;

    // Stage X and W chunk as fp16 swizzled tiles
    {
        const float4* Xg = (const float4*)(X + (size_t)row0 * HH);
        const float4* Wg = (const float4*)(W + (size_t)c * 128 * HH);
        #pragma unroll
        for (int i = 0; i < 16; i++) {
            int idx = tid + i * 256;
            int r = idx >> 5;
            int e0 = (idx & 31) << 2;       // element col, multiple of 4
            int uc = e0 >> 1;               // u32 col, multiple of 2
            int sw = uc ^ ((r & 7) << 2);   // preserves 2-alignment
            float4 v = Xg[idx];
            __half2 h01 = __floats2half2_rn(v.x, v.y);
            __half2 h23 = __floats2half2_rn(v.z, v.w);
            uint2 u;
            u.x = *reinterpret_cast<uint32_t*>(&h01);
            u.y = *reinterpret_cast<uint32_t*>(&h23);
            *(uint2*)(smu + QS_X + r * 64 + sw) = u;
            float4 w = Wg[idx];
            __half2 w01 = __floats2half2_rn(w.x, w.y);
            __half2 w23 = __floats2half2_rn(w.z, w.w);
            uint2 uw;
            uw.x = *reinterpret_cast<uint32_t*>(&w01);
            uw.y = *reinterpret_cast<uint32_t*>(&w23);
            *(uint2*)(smu + QS_W + r * 64 + sw) = uw;
        }
        if (tid < 128) Bs[tid] = bias[c * 128 + tid];
    }
    __syncthreads();

    // GEMM: out[m128, n128] = X . Wchunk^T, warp tile m32 x n64, fp16 MMA
    float acc[2][8][4];
    #pragma unroll
    for (int st = 0; st < 2; st++)
        #pragma unroll
        for (int nt = 0; nt < 8; nt++)
            #pragma unroll
            for (int jj = 0; jj < 4; jj++) acc[st][nt][jj] = 0.0f;

    #pragma unroll
    for (int ks = 0; ks < 8; ks++) {
        const uint32_t col4 = ((uint32_t)(ks * 32)) ^ xhi4;
        uint32_t a0[4], a1[4];
        ldsm_x4(a0, xBase + col4);
        ldsm_x4(a1, xBase + col4 + 4096);
        #pragma unroll
        for (int nb = 0; nb < 4; nb++) {
            uint32_t bw[4];
            ldsm_x4(bw, wBase + (uint32_t)nb * 4096 + col4);
            mma_f16(acc[0][2 * nb],     a0, bw[0], bw[1]);
            mma_f16(acc[1][2 * nb],     a1, bw[0], bw[1]);
            mma_f16(acc[0][2 * nb + 1], a0, bw[2], bw[3]);
            mma_f16(acc[1][2 * nb + 1], a1, bw[2], bw[3]);
        }
    }

    if (c == 2) {
        __syncthreads();   // tile reads done; St overlays X/W
        float* St = (float*)smu;    // 128 x 130 (s rows, h cols)
        #pragma unroll
        for (int st = 0; st < 2; st++) {
            #pragma unroll
            for (int nt = 0; nt < 8; nt++) {
                int col = n0 + nt * 8 + 2 * tg;
                int r0 = m0 + 16 * st + g;
                int r1 = r0 + 8;
                float b0v = Bs[col], b1v = Bs[col + 1];
                *(float2*)(St + r0 * 130 + col) =
                    make_float2(acc[st][nt][0] + b0v, acc[st][nt][1] + b1v);
                *(float2*)(St + r1 * 130 + col) =
                    make_float2(acc[st][nt][2] + b0v, acc[st][nt][3] + b1v);
            }
        }
        __syncthreads();
        const int b = row0 >> 12;
        const int sbase = row0 & 4095;
        const float* Stc = (const float*)smu;
        #pragma unroll 4
        for (int i = 0; i < 64; i++) {
            int idx = tid + i * 256;
            int h = idx >> 7;
            int s = idx & 127;
            g_Vt[((size_t)(b * HH + h)) * SS + sbase + s] = __float2half_rn(Stc[s * 130 + h]);
        }
    } else {
        __half* dst = (c == 0 ? g_Q : g_K) + (size_t)row0 * HH;
        // Q scale folds 1/sqrt(128) AND log2(e): exp(x) = 2^(x*log2e)
        const float scale = (c == 0)
            ? (0.08838834764831845f * 1.4426950408889634f) : 1.0f;
        #pragma unroll
        for (int st = 0; st < 2; st++) {
            #pragma unroll
            for (int nt = 0; nt < 8; nt++) {
                int col = n0 + nt * 8 + 2 * tg;
                int r0 = m0 + 16 * st + g;
                int r1 = r0 + 8;
                float b0v = Bs[col], b1v = Bs[col + 1];
                *(__half2*)(dst + (size_t)r0 * HH + col) =
                    __floats2half2_rn((acc[st][nt][0] + b0v) * scale,
                                      (acc[st][nt][1] + b1v) * scale);
                *(__half2*)(dst + (size_t)r1 * HH + col) =
                    __floats2half2_rn((acc[st][nt][2] + b0v) * scale,
                                      (acc[st][nt][3] + b1v) * scale);
            }
        }
    }
}

// ---------------------------------------------------------------------------
// Kernel 2: flash attention, register-resident P (validated R12) +
// ex2.approx.f16x2 softmax + lsum via ones-MMA (P.1 on tensor pipe).
// 256 threads, 8 warps = 4 m-strips x 2 key-halves.
// SMEM u32: Q[8192] K0 K1 V0 V1 = 160KB. Swizzle u32col^4*(row&7).
// ---------------------------------------------------------------------------
#define UQ  0
#define UK0 8192
#define UV0 24576
#define ULS 16384            // lsum publish area (overlays K1 region, post-loop)
#define SMEM_ATTN (40960 * 4)   // 163840 B

__global__ __launch_bounds__(256, 1) void attn_kernel(float* __restrict__ out)
{
    extern __shared__ uint32_t smu[];
    const uint32_t smem_u32 = smem_u32_of(smu);

    const int tid = threadIdx.x;
    const int wid = tid >> 5;
    const int lane = tid & 31;
    const int g = lane >> 2;
    const int tg = lane & 3;
    const int m0 = (wid >> 1) * 32;   // m-strip
    const int kh = wid & 1;           // key-half
    const int b = blockIdx.y;
    const int q0 = blockIdx.x * 128;

    // ldmatrix per-lane constants (validated R11/R12)
    const int j = lane & 7;
    const int mat = lane >> 3;
    const uint32_t xhi4 = (uint32_t)((4 * j) & 24) << 2;
    const int rowA = j + 8 * (mat & 1);
    const uint32_t xloA = 16u * (((mat >> 1) ^ j) & 1);
    const int rowB = j + 8 * (mat >> 1);
    const uint32_t xloB = 16u * (((mat & 1) ^ j) & 1);

    const uint32_t qBase   = smem_u32 + UQ * 4 + (uint32_t)(m0 + rowA) * 256 + xloA;
    const uint32_t kCommon = smem_u32 + UK0 * 4 + (uint32_t)(kh * 64 + rowB) * 256 + xloB;
    const uint32_t vCommon = smem_u32 + UV0 * 4 + (uint32_t)rowB * 256 + xloB;
    const uint32_t vColOff = (uint32_t)(kh * 128);

    // ---- prologue: stage tile 0 (K,V) + Q ----
    {
        const __half* Kg = g_K + ((size_t)b * SS) * HH;
        const __half* Vg = g_Vt + (size_t)(b * HH) * SS;
        #pragma unroll
        for (int i = 0; i < 8; i++) {
            int idx = tid + i * 256;
            int r = idx >> 4;
            int c4 = (idx & 15) << 2;
            int sw = c4 ^ ((r & 7) << 2);
            cp_async16(smem_u32 + (UK0 + r * 64 + sw) * 4, Kg + r * HH + c4 * 2);
            cp_async16(smem_u32 + (UV0 + r * 64 + sw) * 4, Vg + (size_t)r * SS + c4 * 2);
        }
        CP_COMMIT();
        const __half* Qg = g_Q + ((size_t)b * SS + q0) * HH;
        #pragma unroll
        for (int i = 0; i < 8; i++) {
            int idx = tid + i * 256;
            int r = idx >> 4;
            int c4 = (idx & 15) << 2;
            int sw = c4 ^ ((r & 7) << 2);
            *(uint4*)(smu + UQ + r * 64 + sw) = *(const uint4*)(Qg + r * HH + c4 * 2);
        }
    }

    float oacc[2][16][4];   // partial O: m32 x h128 over this warp's keys
    #pragma unroll
    for (int st = 0; st < 2; st++)
        #pragma unroll
        for (int nt = 0; nt < 16; nt++)
            #pragma unroll
            for (int jj = 0; jj < 4; jj++) oacc[st][nt][jj] = 0.0f;
    float lacc[2][4];       // lsum C-frags (P . ones), rows g / g+8
    #pragma unroll
    for (int st = 0; st < 2; st++)
        #pragma unroll
        for (int jj = 0; jj < 4; jj++) lacc[st][jj] = 0.0f;

    for (int t = 0; t < 32; t++) {
        const uint32_t kBase = kCommon + (uint32_t)(t & 1) * 32768u;
        const uint32_t vBase = vCommon + (uint32_t)(t & 1) * 32768u;

        CP_WAIT0();
        __syncthreads();   // K(t),V(t) visible; prior reads of reused bufs done

        // Prefetch tile t+1
        if (t + 1 < 32) {
            const int ok = UK0 + ((t + 1) & 1) * 8192;
            const int ov = UV0 + ((t + 1) & 1) * 8192;
            const __half* Kg = g_K + ((size_t)b * SS + (t + 1) * 128) * HH;
            const __half* Vg = g_Vt + (size_t)(b * HH) * SS + (t + 1) * 128;
            #pragma unroll
            for (int i = 0; i < 8; i++) {
                int idx = tid + i * 256;
                int r = idx >> 4;
                int c4 = (idx & 15) << 2;
                int sw = c4 ^ ((r & 7) << 2);
                cp_async16(smem_u32 + (ok + r * 64 + sw) * 4, Kg + r * HH + c4 * 2);
                cp_async16(smem_u32 + (ov + r * 64 + sw) * 4, Vg + (size_t)r * SS + c4 * 2);
            }
            CP_COMMIT();
        }

        // --- S = Q . K^T : m32 x n64 (this warp's 64 keys) x k128 ---
        float sacc[2][8][4];
        #pragma unroll
        for (int st = 0; st < 2; st++)
            #pragma unroll
            for (int nt = 0; nt < 8; nt++)
                #pragma unroll
                for (int jj = 0; jj < 4; jj++) sacc[st][nt][jj] = 0.0f;

        #pragma unroll
        for (int ks = 0; ks < 8; ks++) {
            const uint32_t col4 = ((uint32_t)(ks * 32)) ^ xhi4;
            uint32_t qa0[4], qa1[4];
            ldsm_x4(qa0, qBase + col4);
            ldsm_x4(qa1, qBase + col4 + 4096);
            #pragma unroll
            for (int nb = 0; nb < 4; nb++) {
                uint32_t bk[4];
                ldsm_x4(bk, kBase + (uint32_t)nb * 4096 + col4);
                mma_f16(sacc[0][2 * nb],     qa0, bk[0], bk[1]);
                mma_f16(sacc[1][2 * nb],     qa1, bk[0], bk[1]);
                mma_f16(sacc[0][2 * nb + 1], qa0, bk[2], bk[3]);
                mma_f16(sacc[1][2 * nb + 1], qa1, bk[2], bk[3]);
            }
        }

        // --- softmax: pack to half2, ex2.approx.f16x2 -> P fragments ---
        uint32_t pf[4][2][4];   // [k-step][m-subtile][a-frag]
        #pragma unroll
        for (int st = 0; st < 2; st++) {
            #pragma unroll
            for (int nt = 0; nt < 8; nt++) {
                __half2 slo = __floats2half2_rn(sacc[st][nt][0], sacc[st][nt][1]);
                __half2 shi = __floats2half2_rn(sacc[st][nt][2], sacc[st][nt][3]);
                pf[nt >> 1][st][(nt & 1) * 2]     = hex2(*reinterpret_cast<uint32_t*>(&slo));
                pf[nt >> 1][st][(nt & 1) * 2 + 1] = hex2(*reinterpret_cast<uint32_t*>(&shi));
            }
        }

        // --- O += P . V (m32 x h128 x k64) and lsum += P . 1 ---
        #pragma unroll
        for (int kk = 0; kk < 4; kk++) {
            const uint32_t col4v = (vColOff + (uint32_t)(kk * 32)) ^ xhi4;
            mma_f16(lacc[0], pf[kk][0], ONES_H2, ONES_H2);
            mma_f16(lacc[1], pf[kk][1], ONES_H2, ONES_H2);
            #pragma unroll
            for (int hb = 0; hb < 8; hb++) {
                uint32_t bv[4];
                ldsm_x4(bv, vBase + (uint32_t)hb * 4096 + col4v);
                mma_f16(oacc[0][2 * hb],     pf[kk][0], bv[0], bv[1]);
                mma_f16(oacc[1][2 * hb],     pf[kk][1], bv[0], bv[1]);
                mma_f16(oacc[0][2 * hb + 1], pf[kk][0], bv[2], bv[3]);
                mma_f16(oacc[1][2 * hb + 1], pf[kk][1], bv[2], bv[3]);
            }
        }
    }

    // --- combine key-halves: kh=1 publishes partial O + lsum via smem ---
    __syncthreads();   // staging done with smem; safe to reuse
    {
        float* Ocmb = (float*)smu;                 // 4 strips x 32 x 128 f32 = 64KB
        float* LS = (float*)(smu + ULS);           // 128 f32
        if (kh == 1) {
            float* Obase = Ocmb + (m0 >> 5) * 4096;
            #pragma unroll
            for (int st = 0; st < 2; st++) {
                int r0 = 16 * st + g;
                int r1 = r0 + 8;
                if (tg == 0) {
                    LS[m0 + r0] = lacc[st][0];
                    LS[m0 + r1] = lacc[st][2];
                }
                #pragma unroll
                for (int nt = 0; nt < 16; nt++) {
                    int col = nt * 8 + 2 * tg;
                    *(float2*)(Obase + r0 * 128 + col) =
                        make_float2(oacc[st][nt][0], oacc[st][nt][1]);
                    *(float2*)(Obase + r1 * 128 + col) =
                        make_float2(oacc[st][nt][2], oacc[st][nt][3]);
                }
            }
        }
    }
    __syncthreads();

    // --- epilogue: kh=0 combines, normalizes, writes gmem ---
    if (kh == 0) {
        const float* Ocmb = (const float*)smu + (m0 >> 5) * 4096;
        const float* LS = (const float*)(smu + ULS);
        float* og = out + ((size_t)(b * SS) + q0) * HH;
        #pragma unroll
        for (int st = 0; st < 2; st++) {
            int r0 = 16 * st + g;
            int r1 = r0 + 8;
            float inv0 = 1.0f / (lacc[st][0] + LS[m0 + r0]);
            float inv1 = 1.0f / (lacc[st][2] + LS[m0 + r1]);
            float* o0 = og + (size_t)(m0 + r0) * HH;
            float* o1 = og + (size_t)(m0 + r1) * HH;
            #pragma unroll
            for (int nt = 0; nt < 16; nt++) {
                int col = nt * 8 + 2 * tg;
                float2 p0 = *(const float2*)(Ocmb + r0 * 128 + col);
                float2 p1 = *(const float2*)(Ocmb + r1 * 128 + col);
                *(float2*)(o0 + col) = make_float2((oacc[st][nt][0] + p0.x) * inv0,
                                                   (oacc[st][nt][1] + p0.y) * inv0);
                *(float2*)(o1 + col) = make_float2((oacc[st][nt][2] + p1.x) * inv1,
                                                   (oacc[st][nt][3] + p1.y) * inv1);
            }
        }
    }
}

// ---------------------------------------------------------------------------
extern "C" void kernel_launch(void* const* d_in, const int* in_sizes, int n_in,
                              void* d_out, int out_size)
{
    const float* X    = (const float*)d_in[0];   // [4,4096,128]
    const float* W    = (const float*)d_in[1];   // [384,128]
    const float* bias = (const float*)d_in[2];   // [384]
    float* out = (float*)d_out;                  // [4,4096,128]

    cudaFuncSetAttribute(qkv_f16, cudaFuncAttributeMaxDynamicSharedMemorySize, SMEM_QKV);
    cudaFuncSetAttribute(attn_kernel, cudaFuncAttributeMaxDynamicSharedMemorySize, SMEM_ATTN);

    qkv_f16<<<dim3(128, 3), 256, SMEM_QKV>>>(X, W, bias);
    attn_kernel<<<dim3(SS / 128, BB), 256, SMEM_ATTN>>>(out);
}

// round 14
// speedup vs baseline: 1.3816x; 1.0638x over previous
#include <cuda_runtime.h>
#include <cuda_fp16.h>
#include <math.h>
#include <stdint.h>

#define BB 4
#define SS 4096
#define HH 128
#define ROWS_TOTAL (BB * SS)

// Scratch (allocation-free path). Q pre-scaled by log2(e)/sqrt(H). All fp16.
// V stored transposed: g_Vt[b][h][s].
__device__ __half g_Q[ROWS_TOTAL * HH];
__device__ __half g_K[ROWS_TOTAL * HH];
__device__ __half g_Vt[BB * HH * SS];

__device__ __forceinline__ uint32_t hex2(uint32_t h2) {
    uint32_t y;
    asm("ex2.approx.f16x2 %0, %1;" : "=r"(y) : "r"(h2));
    return y;
}

__device__ __forceinline__ uint32_t smem_u32_of(const void* p) {
    uint32_t a;
    asm("{ .reg .u64 t; cvta.to.shared.u64 t, %1; cvt.u32.u64 %0, t; }" : "=r"(a) : "l"(p));
    return a;
}

__device__ __forceinline__ void cp_async16(uint32_t dst, const void* src) {
    asm volatile("cp.async.cg.shared.global [%0], [%1], 16;" :: "r"(dst), "l"(src));
}
#define CP_COMMIT() asm volatile("cp.async.commit_group;" ::: "memory")
#define CP_WAIT0()  asm volatile("cp.async.wait_group 0;" ::: "memory")

__device__ __forceinline__ void ldsm_x4(uint32_t* r, uint32_t addr) {
    asm volatile("ldmatrix.sync.aligned.m8n8.x4.shared.b16 {%0,%1,%2,%3}, [%4];"
        : "=r"(r[0]), "=r"(r[1]), "=r"(r[2]), "=r"(r[3]) : "r"(addr));
}

// fp16 m16n8k16 with fp32 accumulate (validated R9-R13)
__device__ __forceinline__ void mma_f16(float* d, const uint32_t* a,
                                        uint32_t b0, uint32_t b1) {
    asm volatile(
        "mma.sync.aligned.m16n8k16.row.col.f32.f16.f16.f32 "
        "{%0,%1,%2,%3}, {%4,%5,%6,%7}, {%8,%9}, {%0,%1,%2,%3};"
        : "+f"(d[0]), "+f"(d[1]), "+f"(d[2]), "+f"(d[3])
        : "r"(a[0]), "r"(a[1]), "r"(a[2]), "r"(a[3]), "r"(b0), "r"(b1));
}

// fp16 m16n8k16 with fp16 accumulate (full rate; for the S GEMM)
__device__ __forceinline__ void mma_f16h(uint32_t* d, const uint32_t* a,
                                         uint32_t b0, uint32_t b1) {
    asm volatile(
        "mma.sync.aligned.m16n8k16.row.col.f16.f16.f16.f16 "
        "{%0,%1}, {%2,%3,%4,%5}, {%6,%7}, {%0,%1};"
        : "+r"(d[0]), "+r"(d[1])
        : "r"(a[0]), "r"(a[1]), "r"(a[2]), "r"(a[3]), "r"(b0), "r"(b1));
}

#define ONES_H2 0x3C003C00u

// ---------------------------------------------------------------------------
// Kernel 1: QKV projection, single wave. Grid 128, 256 thr. Each CTA stages
// X tile once + ALL 3 W chunks (fp16 swizzled), loops 3 GEMMs.
// chunk 0 -> Q (scaled by log2e/sqrt(H)), 1 -> K, 2 -> V^T (via St overlay).
// SMEM u32: X[8192] W[3*8192] bias[384 f32] = 132608 B.
// ---------------------------------------------------------------------------
#define QS_X 0
#define QS_W 8192
#define QS_BIAS 32768
#define SMEM_QKV ((32768 + 384) * 4)   // 132608 B

__global__ __launch_bounds__(256, 1) void qkv_f16(const float* __restrict__ X,
                                                  const float* __restrict__ W,
                                                  const float* __restrict__ bias)
{
    extern __shared__ uint32_t smu[];
    const uint32_t smem_u32 = smem_u32_of(smu);
    float* Bs = (float*)(smu + QS_BIAS);

    const int tid = threadIdx.x;
    const int wid = tid >> 5;
    const int lane = tid & 31;
    const int g = lane >> 2;
    const int tg = lane & 3;
    const int m0 = (wid >> 1) * 32;
    const int n0 = (wid & 1) * 64;
    const int row0 = blockIdx.x * 128;

    // ldmatrix per-lane constants (validated R11-R13)
    const int j = lane & 7;
    const int mat = lane >> 3;
    const uint32_t xhi4 = (uint32_t)((4 * j) & 24) << 2;
    const int rowA = j + 8 * (mat & 1);
    const uint32_t xloA = 16u * (((mat >> 1) ^ j) & 1);
    const int rowB = j + 8 * (mat >> 1);
    const uint32_t xloB = 16u * (((mat & 1) ^ j) & 1);

    const uint32_t xBase = smem_u32 + QS_X * 4 + (uint32_t)(m0 + rowA) * 256 + xloA;
    const uint32_t wBase0 = smem_u32 + QS_W * 4 + (uint32_t)(n0 + rowB) * 256 + xloB;

    // Stage X (128 rows) and all W (384 rows) as fp16 swizzled tiles
    {
        const float4* Xg = (const float4*)(X + (size_t)row0 * HH);
        #pragma unroll
        for (int i = 0; i < 16; i++) {
            int idx = tid + i * 256;
            int r = idx >> 5;
            int uc = (idx & 31) << 1;       // u32 col, multiple of 2
            int sw = uc ^ ((r & 7) << 2);
            float4 v = Xg[idx];
            __half2 h01 = __floats2half2_rn(v.x, v.y);
            __half2 h23 = __floats2half2_rn(v.z, v.w);
            uint2 u;
            u.x = *reinterpret_cast<uint32_t*>(&h01);
            u.y = *reinterpret_cast<uint32_t*>(&h23);
            *(uint2*)(smu + QS_X + r * 64 + sw) = u;
        }
        const float4* Wg = (const float4*)W;
        #pragma unroll
        for (int i = 0; i < 48; i++) {
            int idx = tid + i * 256;
            int r = idx >> 5;               // 0..383
            int uc = (idx & 31) << 1;
            int sw = uc ^ ((r & 7) << 2);
            float4 w = Wg[idx];
            __half2 w01 = __floats2half2_rn(w.x, w.y);
            __half2 w23 = __floats2half2_rn(w.z, w.w);
            uint2 uw;
            uw.x = *reinterpret_cast<uint32_t*>(&w01);
            uw.y = *reinterpret_cast<uint32_t*>(&w23);
            *(uint2*)(smu + QS_W + (r >> 7) * 8192 + (r & 127) * 64 + sw) = uw;
        }
        Bs[tid] = bias[tid];
        if (tid < 128) Bs[256 + tid] = bias[256 + tid];
    }
    __syncthreads();

    #pragma unroll 1
    for (int c = 0; c < 3; c++) {
        const uint32_t wBase = wBase0 + (uint32_t)c * 32768u;
        const float* Bc = Bs + c * 128;

        float acc[2][8][4];
        #pragma unroll
        for (int st = 0; st < 2; st++)
            #pragma unroll
            for (int nt = 0; nt < 8; nt++)
                #pragma unroll
                for (int jj = 0; jj < 4; jj++) acc[st][nt][jj] = 0.0f;

        #pragma unroll
        for (int ks = 0; ks < 8; ks++) {
            const uint32_t col4 = ((uint32_t)(ks * 32)) ^ xhi4;
            uint32_t a0[4], a1[4];
            ldsm_x4(a0, xBase + col4);
            ldsm_x4(a1, xBase + col4 + 4096);
            #pragma unroll
            for (int nb = 0; nb < 4; nb++) {
                uint32_t bw[4];
                ldsm_x4(bw, wBase + (uint32_t)nb * 4096 + col4);
                mma_f16(acc[0][2 * nb],     a0, bw[0], bw[1]);
                mma_f16(acc[1][2 * nb],     a1, bw[0], bw[1]);
                mma_f16(acc[0][2 * nb + 1], a0, bw[2], bw[3]);
                mma_f16(acc[1][2 * nb + 1], a1, bw[2], bw[3]);
            }
        }

        if (c == 2) {
            __syncthreads();   // all GEMM reads done; St overlays X/W0
            float* St = (float*)smu;    // 128 x 130 (s rows, h cols)
            #pragma unroll
            for (int st = 0; st < 2; st++) {
                #pragma unroll
                for (int nt = 0; nt < 8; nt++) {
                    int col = n0 + nt * 8 + 2 * tg;
                    int r0 = m0 + 16 * st + g;
                    int r1 = r0 + 8;
                    float b0v = Bc[col], b1v = Bc[col + 1];
                    *(float2*)(St + r0 * 130 + col) =
                        make_float2(acc[st][nt][0] + b0v, acc[st][nt][1] + b1v);
                    *(float2*)(St + r1 * 130 + col) =
                        make_float2(acc[st][nt][2] + b0v, acc[st][nt][3] + b1v);
                }
            }
            __syncthreads();
            const int b = row0 >> 12;
            const int sbase = row0 & 4095;
            const float* Stc = (const float*)smu;
            #pragma unroll 4
            for (int i = 0; i < 64; i++) {
                int idx = tid + i * 256;
                int h = idx >> 7;
                int s = idx & 127;
                g_Vt[((size_t)(b * HH + h)) * SS + sbase + s] =
                    __float2half_rn(Stc[s * 130 + h]);
            }
        } else {
            __half* dst = (c == 0 ? g_Q : g_K) + (size_t)row0 * HH;
            // Q scale folds 1/sqrt(128) AND log2(e): exp(x) = 2^(x*log2e)
            const float scale = (c == 0)
                ? (0.08838834764831845f * 1.4426950408889634f) : 1.0f;
            #pragma unroll
            for (int st = 0; st < 2; st++) {
                #pragma unroll
                for (int nt = 0; nt < 8; nt++) {
                    int col = n0 + nt * 8 + 2 * tg;
                    int r0 = m0 + 16 * st + g;
                    int r1 = r0 + 8;
                    float b0v = Bc[col], b1v = Bc[col + 1];
                    *(__half2*)(dst + (size_t)r0 * HH + col) =
                        __floats2half2_rn((acc[st][nt][0] + b0v) * scale,
                                          (acc[st][nt][1] + b1v) * scale);
                    *(__half2*)(dst + (size_t)r1 * HH + col) =
                        __floats2half2_rn((acc[st][nt][2] + b0v) * scale,
                                          (acc[st][nt][3] + b1v) * scale);
                }
            }
        }
    }
}

// ---------------------------------------------------------------------------
// Kernel 2: flash attention. Register-resident P (R12), ones-MMA lsum (R13),
// S-GEMM now fp16-ACCUMULATE (full-rate HMMA; C-frag is hex2 input directly).
// PV + lsum stay fp32-accumulate. 256 threads, 8 warps = 4 m-strips x 2 kh.
// SMEM u32: Q[8192] K0 K1 V0 V1 = 160KB. Swizzle u32col^4*(row&7).
// ---------------------------------------------------------------------------
#define UQ  0
#define UK0 8192
#define UV0 24576
#define ULS 16384            // lsum publish area (overlays K1 region, post-loop)
#define SMEM_ATTN (40960 * 4)   // 163840 B

__global__ __launch_bounds__(256, 1) void attn_kernel(float* __restrict__ out)
{
    extern __shared__ uint32_t smu[];
    const uint32_t smem_u32 = smem_u32_of(smu);

    const int tid = threadIdx.x;
    const int wid = tid >> 5;
    const int lane = tid & 31;
    const int g = lane >> 2;
    const int tg = lane & 3;
    const int m0 = (wid >> 1) * 32;   // m-strip
    const int kh = wid & 1;           // key-half
    const int b = blockIdx.y;
    const int q0 = blockIdx.x * 128;

    // ldmatrix per-lane constants (validated R11-R13)
    const int j = lane & 7;
    const int mat = lane >> 3;
    const uint32_t xhi4 = (uint32_t)((4 * j) & 24) << 2;
    const int rowA = j + 8 * (mat & 1);
    const uint32_t xloA = 16u * (((mat >> 1) ^ j) & 1);
    const int rowB = j + 8 * (mat >> 1);
    const uint32_t xloB = 16u * (((mat & 1) ^ j) & 1);

    const uint32_t qBase   = smem_u32 + UQ * 4 + (uint32_t)(m0 + rowA) * 256 + xloA;
    const uint32_t kCommon = smem_u32 + UK0 * 4 + (uint32_t)(kh * 64 + rowB) * 256 + xloB;
    const uint32_t vCommon = smem_u32 + UV0 * 4 + (uint32_t)rowB * 256 + xloB;
    const uint32_t vColOff = (uint32_t)(kh * 128);

    // ---- prologue: stage tile 0 (K,V) + Q ----
    {
        const __half* Kg = g_K + ((size_t)b * SS) * HH;
        const __half* Vg = g_Vt + (size_t)(b * HH) * SS;
        #pragma unroll
        for (int i = 0; i < 8; i++) {
            int idx = tid + i * 256;
            int r = idx >> 4;
            int c4 = (idx & 15) << 2;
            int sw = c4 ^ ((r & 7) << 2);
            cp_async16(smem_u32 + (UK0 + r * 64 + sw) * 4, Kg + r * HH + c4 * 2);
            cp_async16(smem_u32 + (UV0 + r * 64 + sw) * 4, Vg + (size_t)r * SS + c4 * 2);
        }
        CP_COMMIT();
        const __half* Qg = g_Q + ((size_t)b * SS + q0) * HH;
        #pragma unroll
        for (int i = 0; i < 8; i++) {
            int idx = tid + i * 256;
            int r = idx >> 4;
            int c4 = (idx & 15) << 2;
            int sw = c4 ^ ((r & 7) << 2);
            *(uint4*)(smu + UQ + r * 64 + sw) = *(const uint4*)(Qg + r * HH + c4 * 2);
        }
    }

    float oacc[2][16][4];   // partial O: m32 x h128 over this warp's keys
    #pragma unroll
    for (int st = 0; st < 2; st++)
        #pragma unroll
        for (int nt = 0; nt < 16; nt++)
            #pragma unroll
            for (int jj = 0; jj < 4; jj++) oacc[st][nt][jj] = 0.0f;
    float lacc[2][4];       // lsum C-frags (P . ones), rows g / g+8
    #pragma unroll
    for (int st = 0; st < 2; st++)
        #pragma unroll
        for (int jj = 0; jj < 4; jj++) lacc[st][jj] = 0.0f;

    for (int t = 0; t < 32; t++) {
        const uint32_t kBase = kCommon + (uint32_t)(t & 1) * 32768u;
        const uint32_t vBase = vCommon + (uint32_t)(t & 1) * 32768u;

        CP_WAIT0();
        __syncthreads();   // K(t),V(t) visible; prior reads of reused bufs done

        // Prefetch tile t+1
        if (t + 1 < 32) {
            const int ok = UK0 + ((t + 1) & 1) * 8192;
            const int ov = UV0 + ((t + 1) & 1) * 8192;
            const __half* Kg = g_K + ((size_t)b * SS + (t + 1) * 128) * HH;
            const __half* Vg = g_Vt + (size_t)(b * HH) * SS + (t + 1) * 128;
            #pragma unroll
            for (int i = 0; i < 8; i++) {
                int idx = tid + i * 256;
                int r = idx >> 4;
                int c4 = (idx & 15) << 2;
                int sw = c4 ^ ((r & 7) << 2);
                cp_async16(smem_u32 + (ok + r * 64 + sw) * 4, Kg + r * HH + c4 * 2);
                cp_async16(smem_u32 + (ov + r * 64 + sw) * 4, Vg + (size_t)r * SS + c4 * 2);
            }
            CP_COMMIT();
        }

        // --- S = Q . K^T : m32 x n64 x k128, fp16 ACCUMULATE (full rate) ---
        uint32_t sacc[2][8][2];
        #pragma unroll
        for (int st = 0; st < 2; st++)
            #pragma unroll
            for (int nt = 0; nt < 8; nt++) {
                sacc[st][nt][0] = 0u;
                sacc[st][nt][1] = 0u;
            }

        #pragma unroll
        for (int ks = 0; ks < 8; ks++) {
            const uint32_t col4 = ((uint32_t)(ks * 32)) ^ xhi4;
            uint32_t qa0[4], qa1[4];
            ldsm_x4(qa0, qBase + col4);
            ldsm_x4(qa1, qBase + col4 + 4096);
            #pragma unroll
            for (int nb = 0; nb < 4; nb++) {
                uint32_t bk[4];
                ldsm_x4(bk, kBase + (uint32_t)nb * 4096 + col4);
                mma_f16h(sacc[0][2 * nb],     qa0, bk[0], bk[1]);
                mma_f16h(sacc[1][2 * nb],     qa1, bk[0], bk[1]);
                mma_f16h(sacc[0][2 * nb + 1], qa0, bk[2], bk[3]);
                mma_f16h(sacc[1][2 * nb + 1], qa1, bk[2], bk[3]);
            }
        }

        // --- softmax: f16 C-frag -> ex2.approx.f16x2 directly (no cvt!) ---
        uint32_t pf[4][2][4];   // [k-step][m-subtile][a-frag]
        #pragma unroll
        for (int st = 0; st < 2; st++) {
            #pragma unroll
            for (int nt = 0; nt < 8; nt++) {
                pf[nt >> 1][st][(nt & 1) * 2]     = hex2(sacc[st][nt][0]);
                pf[nt >> 1][st][(nt & 1) * 2 + 1] = hex2(sacc[st][nt][1]);
            }
        }

        // --- O += P . V (m32 x h128 x k64) and lsum += P . 1 (f32 acc) ---
        #pragma unroll
        for (int kk = 0; kk < 4; kk++) {
            const uint32_t col4v = (vColOff + (uint32_t)(kk * 32)) ^ xhi4;
            mma_f16(lacc[0], pf[kk][0], ONES_H2, ONES_H2);
            mma_f16(lacc[1], pf[kk][1], ONES_H2, ONES_H2);
            #pragma unroll
            for (int hb = 0; hb < 8; hb++) {
                uint32_t bv[4];
                ldsm_x4(bv, vBase + (uint32_t)hb * 4096 + col4v);
                mma_f16(oacc[0][2 * hb],     pf[kk][0], bv[0], bv[1]);
                mma_f16(oacc[1][2 * hb],     pf[kk][1], bv[0], bv[1]);
                mma_f16(oacc[0][2 * hb + 1], pf[kk][0], bv[2], bv[3]);
                mma_f16(oacc[1][2 * hb + 1], pf[kk][1], bv[2], bv[3]);
            }
        }
    }

    // --- combine key-halves: kh=1 publishes partial O + lsum via smem ---
    __syncthreads();   // staging done with smem; safe to reuse
    {
        float* Ocmb = (float*)smu;                 // 4 strips x 32 x 128 f32 = 64KB
        float* LS = (float*)(smu + ULS);           // 128 f32
        if (kh == 1) {
            float* Obase = Ocmb + (m0 >> 5) * 4096;
            #pragma unroll
            for (int st = 0; st < 2; st++) {
                int r0 = 16 * st + g;
                int r1 = r0 + 8;
                if (tg == 0) {
                    LS[m0 + r0] = lacc[st][0];
                    LS[m0 + r1] = lacc[st][2];
                }
                #pragma unroll
                for (int nt = 0; nt < 16; nt++) {
                    int col = nt * 8 + 2 * tg;
                    *(float2*)(Obase + r0 * 128 + col) =
                        make_float2(oacc[st][nt][0], oacc[st][nt][1]);
                    *(float2*)(Obase + r1 * 128 + col) =
                        make_float2(oacc[st][nt][2], oacc[st][nt][3]);
                }
            }
        }
    }
    __syncthreads();

    // --- epilogue: kh=0 combines, normalizes, writes gmem ---
    if (kh == 0) {
        const float* Ocmb = (const float*)smu + (m0 >> 5) * 4096;
        const float* LS = (const float*)(smu + ULS);
        float* og = out + ((size_t)(b * SS) + q0) * HH;
        #pragma unroll
        for (int st = 0; st < 2; st++) {
            int r0 = 16 * st + g;
            int r1 = r0 + 8;
            float inv0 = 1.0f / (lacc[st][0] + LS[m0 + r0]);
            float inv1 = 1.0f / (lacc[st][2] + LS[m0 + r1]);
            float* o0 = og + (size_t)(m0 + r0) * HH;
            float* o1 = og + (size_t)(m0 + r1) * HH;
            #pragma unroll
            for (int nt = 0; nt < 16; nt++) {
                int col = nt * 8 + 2 * tg;
                float2 p0 = *(const float2*)(Ocmb + r0 * 128 + col);
                float2 p1 = *(const float2*)(Ocmb + r1 * 128 + col);
                *(float2*)(o0 + col) = make_float2((oacc[st][nt][0] + p0.x) * inv0,
                                                   (oacc[st][nt][1] + p0.y) * inv0);
                *(float2*)(o1 + col) = make_float2((oacc[st][nt][2] + p1.x) * inv1,
                                                   (oacc[st][nt][3] + p1.y) * inv1);
            }
        }
    }
}

// ---------------------------------------------------------------------------
extern "C" void kernel_launch(void* const* d_in, const int* in_sizes, int n_in,
                              void* d_out, int out_size)
{
    const float* X    = (const float*)d_in[0];   // [4,4096,128]
    const float* W    = (const float*)d_in[1];   // [384,128]
    const float* bias = (const float*)d_in[2];   // [384]
    float* out = (float*)d_out;                  // [4,4096,128]

    cudaFuncSetAttribute(qkv_f16, cudaFuncAttributeMaxDynamicSharedMemorySize, SMEM_QKV);
    cudaFuncSetAttribute(attn_kernel, cudaFuncAttributeMaxDynamicSharedMemorySize, SMEM_ATTN);

    qkv_f16<<<128, 256, SMEM_QKV>>>(X, W, bias);
    attn_kernel<<<dim3(SS / 128, BB), 256, SMEM_ATTN>>>(out);
}